// round 1
// baseline (speedup 1.0000x reference)
#include <cuda_runtime.h>
#include <cuda_bf16.h>
#include <mma.h>
#include <math.h>

using namespace nvcuda;

// ---------------- problem constants ----------------
constexpr int  B_   = 8;
constexpr int  C_   = 256;
constexpr int  H_   = 200;
constexpr int  W_   = 200;
constexpr int  WS_  = 7;
constexpr int  HP_  = 203;          // padded H (29*7)
constexpr int  WP_  = 203;          // padded W
constexpr int  NWH  = 29;
constexpr int  NWW  = 29;
constexpr int  NWIN = B_ * NWH * NWW;      // 6728
constexpr size_t M_TOT = (size_t)B_ * HP_ * WP_;  // 329672 tokens
constexpr int  DFF  = 1024;

// ---------------- scratch buffers (device globals; no allocations allowed) ----------------
__device__ float          g_xpad[M_TOT * 256];   // channels-last padded input (x, zero padded)
__device__ __nv_bfloat16  g_z   [M_TOT * 256];   // LN1 output
__device__ __nv_bfloat16  g_qkv [M_TOT * 768];   // QKV (q pre-scaled by 1/sqrt(32))
__device__ __nv_bfloat16  g_o   [M_TOT * 256];   // attention output
__device__ float          g_s2  [M_TOT * 256];   // s + attn proj (residual stream, fp32)
__device__ __nv_bfloat16  g_h   [M_TOT * 256];   // LN2 output
__device__ __nv_bfloat16  g_g   [M_TOT * 1024];  // gelu(ff1) output
__device__ float          g_y   [M_TOT * 256];   // final channels-last output

__device__ __nv_bfloat16  g_wqkv[768 * 256];
__device__ __nv_bfloat16  g_wo  [256 * 256];
__device__ __nv_bfloat16  g_w1  [1024 * 256];
__device__ __nv_bfloat16  g_w2  [256 * 1024];

// ---------------- fp32 -> bf16 weight convert ----------------
__global__ void cvt_kernel(const float* __restrict__ a, __nv_bfloat16* __restrict__ o, int n) {
    int i = blockIdx.x * 256 + threadIdx.x;
    if (i < n) o[i] = __float2bfloat16(a[i]);
}

// ---------------- NCHW -> padded channels-last transpose ----------------
__global__ void tin_kernel(const float* __restrict__ x, float* __restrict__ xp) {
    __shared__ float tile[32][33];
    int b = blockIdx.z / HP_, h = blockIdx.z % HP_;
    int wx = blockIdx.x * 32, cx = blockIdx.y * 32;
    int tx = threadIdx.x, ty = threadIdx.y;
#pragma unroll
    for (int j = 0; j < 4; j++) {
        int c = cx + ty + j * 8;
        int w = wx + tx;
        float val = 0.f;
        if (h < H_ && w < W_)
            val = x[(((size_t)b * C_ + c) * H_ + h) * W_ + w];
        tile[ty + j * 8][tx] = val;     // tile[c_local][w_local]
    }
    __syncthreads();
#pragma unroll
    for (int j = 0; j < 4; j++) {
        int w = wx + ty + j * 8;
        int c = cx + tx;
        if (w < WP_)
            xp[(((size_t)(b * HP_ + h)) * WP_ + w) * C_ + c] = tile[tx][ty + j * 8];
    }
}

// ---------------- channels-last -> NCHW (cropped) output transpose ----------------
__global__ void tout_kernel(const float* __restrict__ y, float* __restrict__ out) {
    __shared__ float tile[32][33];
    int b = blockIdx.z / H_, h = blockIdx.z % H_;
    int wx = blockIdx.x * 32, cx = blockIdx.y * 32;
    int tx = threadIdx.x, ty = threadIdx.y;
#pragma unroll
    for (int j = 0; j < 4; j++) {
        int w = wx + ty + j * 8;
        int c = cx + tx;
        if (w < W_)
            tile[ty + j * 8][tx] = y[(((size_t)(b * HP_ + h)) * WP_ + w) * C_ + c]; // tile[w_l][c_l]
    }
    __syncthreads();
#pragma unroll
    for (int j = 0; j < 4; j++) {
        int c = cx + ty + j * 8;
        int w = wx + tx;
        if (w < W_)
            out[(((size_t)b * C_ + c) * H_ + h) * W_ + w] = tile[tx][ty + j * 8];
    }
}

// ---------------- LayerNorm (one warp per token, C=256) ----------------
// in: fp32 rows; pos != nullptr -> add pos_embed[t] first (LN1 over x+pos)
__global__ void __launch_bounds__(256) ln_kernel(
    const float* __restrict__ in, const float* __restrict__ pos,
    const float* __restrict__ gw, const float* __restrict__ gb,
    __nv_bfloat16* __restrict__ out, int M)
{
    int m = blockIdx.x * 8 + (threadIdx.x >> 5);
    int lane = threadIdx.x & 31;
    if (m >= M) return;
    size_t base = (size_t)m * 256 + lane * 8;
    float4 a0 = *(const float4*)(in + base);
    float4 a1 = *(const float4*)(in + base + 4);
    float v[8] = {a0.x, a0.y, a0.z, a0.w, a1.x, a1.y, a1.z, a1.w};
    if (pos) {
        int iw = m % WP_, ih = (m / WP_) % HP_;
        int t = (ih % WS_) * WS_ + (iw % WS_);
        const float* pr = pos + (size_t)t * 256 + lane * 8;
        float4 p0 = *(const float4*)pr;
        float4 p1 = *(const float4*)(pr + 4);
        v[0] += p0.x; v[1] += p0.y; v[2] += p0.z; v[3] += p0.w;
        v[4] += p1.x; v[5] += p1.y; v[6] += p1.z; v[7] += p1.w;
    }
    float s = 0.f, sq = 0.f;
#pragma unroll
    for (int i = 0; i < 8; i++) { s += v[i]; sq += v[i] * v[i]; }
#pragma unroll
    for (int o = 16; o; o >>= 1) {
        s  += __shfl_xor_sync(0xffffffffu, s,  o);
        sq += __shfl_xor_sync(0xffffffffu, sq, o);
    }
    float mean = s * (1.f / 256.f);
    float var  = sq * (1.f / 256.f) - mean * mean;
    float inv  = rsqrtf(var + 1e-5f);
    float4 w0 = *(const float4*)(gw + lane * 8);
    float4 w1 = *(const float4*)(gw + lane * 8 + 4);
    float4 b0 = *(const float4*)(gb + lane * 8);
    float4 b1 = *(const float4*)(gb + lane * 8 + 4);
    float wv[8] = {w0.x, w0.y, w0.z, w0.w, w1.x, w1.y, w1.z, w1.w};
    float bv[8] = {b0.x, b0.y, b0.z, b0.w, b1.x, b1.y, b1.z, b1.w};
    union { uint4 u; __nv_bfloat16 h[8]; } pk;
#pragma unroll
    for (int i = 0; i < 8; i++)
        pk.h[i] = __float2bfloat16((v[i] - mean) * inv * wv[i] + bv[i]);
    *(uint4*)(out + base) = pk.u;
}

// ---------------- generic bf16 tensor-core GEMM  C = A(MxK) * W(NxK)^T ----------------
// EPI 0: qkv (scale q cols by 1/sqrt(32), store bf16)
// EPI 1: proj (add bias + xpad + pos, store fp32 -> s2)
// EPI 2: ff1  (gelu(acc+bias), store bf16)
// EPI 3: ff2  (acc + bias + s2, store fp32 -> y)
template <int EPI>
__global__ void __launch_bounds__(256) gemm_bf16(
    const __nv_bfloat16* __restrict__ A, const __nv_bfloat16* __restrict__ Wt,
    const float* __restrict__ bias, int M, int K, int NOUT,
    __nv_bfloat16* __restrict__ outb, float* __restrict__ outf,
    const float* __restrict__ resid, const float* __restrict__ pos)
{
    __shared__ __nv_bfloat16 As[128][40];
    __shared__ __nv_bfloat16 Bs[64][40];
    __shared__ float         Cs[128][64];

    const int n0 = blockIdx.x * 64;
    const int m0 = blockIdx.y * 128;
    const int tid = threadIdx.x;

    wmma::fragment<wmma::accumulator, 16, 16, 16, float> acc[2][2];
#pragma unroll
    for (int mi = 0; mi < 2; mi++)
#pragma unroll
        for (int ni = 0; ni < 2; ni++)
            wmma::fill_fragment(acc[mi][ni], 0.f);

    const int wid = tid >> 5;
    const int wm = wid >> 1, wn = wid & 1;
    const int kt_iters = K / 32;

    for (int kt = 0; kt < kt_iters; kt++) {
        __syncthreads();
        // load A tile 128x32 (2 uint4 per thread)
#pragma unroll
        for (int it = 0; it < 2; it++) {
            int i = tid + it * 256;
            int r = i >> 2, cc = (i & 3) * 8;
            int m = m0 + r;
            uint4 val = make_uint4(0, 0, 0, 0);
            if (m < M) val = *(const uint4*)(A + (size_t)m * K + kt * 32 + cc);
            *(uint4*)&As[r][cc] = val;
        }
        // load B tile 64x32 (1 uint4 per thread)
        {
            int r = tid >> 2, cc = (tid & 3) * 8;
            *(uint4*)&Bs[r][cc] = *(const uint4*)(Wt + (size_t)(n0 + r) * K + kt * 32 + cc);
        }
        __syncthreads();
#pragma unroll
        for (int kk = 0; kk < 32; kk += 16) {
            wmma::fragment<wmma::matrix_a, 16, 16, 16, __nv_bfloat16, wmma::row_major> af[2];
#pragma unroll
            for (int mi = 0; mi < 2; mi++)
                wmma::load_matrix_sync(af[mi], &As[wm * 32 + mi * 16][kk], 40);
#pragma unroll
            for (int ni = 0; ni < 2; ni++) {
                wmma::fragment<wmma::matrix_b, 16, 16, 16, __nv_bfloat16, wmma::col_major> bf;
                wmma::load_matrix_sync(bf, &Bs[wn * 32 + ni * 16][kk], 40);
#pragma unroll
                for (int mi = 0; mi < 2; mi++)
                    wmma::mma_sync(acc[mi][ni], af[mi], bf, acc[mi][ni]);
            }
        }
    }
    __syncthreads();
#pragma unroll
    for (int mi = 0; mi < 2; mi++)
#pragma unroll
        for (int ni = 0; ni < 2; ni++)
            wmma::store_matrix_sync(&Cs[wm * 32 + mi * 16][wn * 32 + ni * 16],
                                    acc[mi][ni], 64, wmma::mem_row_major);
    __syncthreads();

    const int col = tid & 63;
    const int nglob = n0 + col;
    const float bv = bias[nglob];
    for (int rr = tid >> 6; rr < 128; rr += 4) {
        int m = m0 + rr;
        if (m >= M) break;
        float v = Cs[rr][col] + bv;
        if (EPI == 0) {
            if (nglob < 256) v *= 0.17677669529663689f;  // 1/sqrt(32) folded into q
            outb[(size_t)m * NOUT + nglob] = __float2bfloat16(v);
        } else if (EPI == 1) {
            int iw = m % WP_, ih = (m / WP_) % HP_;
            int t = (ih % WS_) * WS_ + (iw % WS_);
            v += resid[(size_t)m * 256 + nglob] + pos[(size_t)t * 256 + nglob];
            outf[(size_t)m * 256 + nglob] = v;
        } else if (EPI == 2) {
            float gl = 0.5f * v * (1.f + erff(v * 0.7071067811865475f));
            outb[(size_t)m * NOUT + nglob] = __float2bfloat16(gl);
        } else {
            v += resid[(size_t)m * 256 + nglob];
            outf[(size_t)m * 256 + nglob] = v;
        }
    }
}

// ---------------- windowed attention: 1 CTA / window, 1 warp / head ----------------
// smem layout (bytes):
//   q: [0,32768)  k: [32768,65536)  v: [65536,98304)   each 8 heads x 64 rows x 32 bf16
//   s: [98304,131072)  8 warps x 16x64 fp32
//   p: [131072,147456) 8 warps x 16x64 bf16
//   o: [147456,163840) 8 warps x 16x32 fp32
__global__ void __launch_bounds__(256) attn_kernel(
    const __nv_bfloat16* __restrict__ qkv, __nv_bfloat16* __restrict__ og)
{
    extern __shared__ char smem[];
    __nv_bfloat16* q_s = (__nv_bfloat16*)smem;
    __nv_bfloat16* k_s = q_s + 8 * 64 * 32;
    __nv_bfloat16* v_s = k_s + 8 * 64 * 32;
    float*         s_s = (float*)(smem + 98304);
    __nv_bfloat16* p_s = (__nv_bfloat16*)(smem + 131072);
    float*         o_s = (float*)(smem + 147456);

    const int win = blockIdx.x;
    const int b = win / (NWH * NWW);
    const int r = win % (NWH * NWW);
    const int wh = r / NWW, ww = r % NWW;
    const int tid = threadIdx.x;

    // gather qkv rows of this window into per-head padded smem
    for (int i = tid; i < 49 * 96; i += 256) {
        int t = i / 96, ch = i % 96;
        int c0 = ch * 8;
        int ih = wh * WS_ + t / WS_, iw = ww * WS_ + t % WS_;
        size_t row = ((size_t)(b * HP_ + ih)) * WP_ + iw;
        uint4 val = *(const uint4*)(qkv + row * 768 + c0);
        int which = c0 >> 8;           // 0=q 1=k 2=v
        int cl = c0 & 255;
        int head = cl >> 5, d = cl & 31;
        __nv_bfloat16* base = (which == 0) ? q_s : (which == 1) ? k_s : v_s;
        *(uint4*)(base + head * 2048 + t * 32 + d) = val;
    }
    // zero pad rows t = 49..63 of q,k,v
    for (int i = tid; i < 1440; i += 256) {
        int a = i / 480, rem = i % 480;
        int head = rem / 60, rr = rem % 60;
        int t = 49 + rr / 4, d = (rr % 4) * 8;
        __nv_bfloat16* base = (a == 0) ? q_s : (a == 1) ? k_s : v_s;
        *(uint4*)(base + head * 2048 + t * 32 + d) = make_uint4(0, 0, 0, 0);
    }
    __syncthreads();

    const int warp = tid >> 5, lane = tid & 31;
    const __nv_bfloat16* qh = q_s + warp * 2048;
    const __nv_bfloat16* kh = k_s + warp * 2048;
    const __nv_bfloat16* vh = v_s + warp * 2048;
    float*         sw = s_s + warp * (16 * 64);
    __nv_bfloat16* pw = p_s + warp * (16 * 64);
    float*         ow = o_s + warp * (16 * 32);

    for (int rt = 0; rt < 4; rt++) {
        // S tile (16 x 64) = Q_rows * K^T  (scale already folded into q)
        wmma::fragment<wmma::accumulator, 16, 16, 16, float> acc[4];
#pragma unroll
        for (int ct = 0; ct < 4; ct++) wmma::fill_fragment(acc[ct], 0.f);
#pragma unroll
        for (int kk = 0; kk < 32; kk += 16) {
            wmma::fragment<wmma::matrix_a, 16, 16, 16, __nv_bfloat16, wmma::row_major> af;
            wmma::load_matrix_sync(af, qh + (rt * 16) * 32 + kk, 32);
#pragma unroll
            for (int ct = 0; ct < 4; ct++) {
                wmma::fragment<wmma::matrix_b, 16, 16, 16, __nv_bfloat16, wmma::col_major> bf;
                wmma::load_matrix_sync(bf, kh + (ct * 16) * 32 + kk, 32);
                wmma::mma_sync(acc[ct], af, bf, acc[ct]);
            }
        }
#pragma unroll
        for (int ct = 0; ct < 4; ct++)
            wmma::store_matrix_sync(sw + ct * 16, acc[ct], 64, wmma::mem_row_major);
        __syncwarp();

        // row softmax over 49 valid cols
        for (int rr2 = 0; rr2 < 16; rr2++) {
            float v0 = sw[rr2 * 64 + lane];
            float v1 = (lane < 17) ? sw[rr2 * 64 + lane + 32] : -1e30f;
            float mx = fmaxf(v0, v1);
#pragma unroll
            for (int o = 16; o; o >>= 1) mx = fmaxf(mx, __shfl_xor_sync(0xffffffffu, mx, o));
            float e0 = __expf(v0 - mx);
            float e1 = (lane < 17) ? __expf(v1 - mx) : 0.f;
            float sm = e0 + e1;
#pragma unroll
            for (int o = 16; o; o >>= 1) sm += __shfl_xor_sync(0xffffffffu, sm, o);
            float inv = 1.f / sm;
            pw[rr2 * 64 + lane]      = __float2bfloat16(e0 * inv);
            pw[rr2 * 64 + lane + 32] = __float2bfloat16(e1 * inv);
        }
        __syncwarp();

        // O tile (16 x 32) = P * V
        wmma::fragment<wmma::accumulator, 16, 16, 16, float> acc2[2];
        wmma::fill_fragment(acc2[0], 0.f);
        wmma::fill_fragment(acc2[1], 0.f);
#pragma unroll
        for (int kk = 0; kk < 4; kk++) {
            wmma::fragment<wmma::matrix_a, 16, 16, 16, __nv_bfloat16, wmma::row_major> pf;
            wmma::load_matrix_sync(pf, pw + kk * 16, 64);
#pragma unroll
            for (int ni = 0; ni < 2; ni++) {
                wmma::fragment<wmma::matrix_b, 16, 16, 16, __nv_bfloat16, wmma::row_major> vf;
                wmma::load_matrix_sync(vf, vh + (kk * 16) * 32 + ni * 16, 32);
                wmma::mma_sync(acc2[ni], pf, vf, acc2[ni]);
            }
        }
        wmma::store_matrix_sync(ow, acc2[0], 32, wmma::mem_row_major);
        wmma::store_matrix_sync(ow + 16, acc2[1], 32, wmma::mem_row_major);
        __syncwarp();

        for (int rr2 = 0; rr2 < 16; rr2++) {
            int t = rt * 16 + rr2;
            if (t >= 49) break;
            int ih = wh * WS_ + t / WS_, iw = ww * WS_ + t % WS_;
            size_t row = ((size_t)(b * HP_ + ih)) * WP_ + iw;
            og[row * 256 + warp * 32 + lane] = __float2bfloat16(ow[rr2 * 32 + lane]);
        }
        __syncwarp();
    }
}

// ---------------- launch ----------------
extern "C" void kernel_launch(void* const* d_in, const int* in_sizes, int n_in,
                              void* d_out, int out_size)
{
    const float* x          = (const float*)d_in[0];
    const float* pos        = (const float*)d_in[1];
    const float* in_proj_w  = (const float*)d_in[2];
    const float* in_proj_b  = (const float*)d_in[3];
    const float* out_proj_w = (const float*)d_in[4];
    const float* out_proj_b = (const float*)d_in[5];
    const float* ln1_w      = (const float*)d_in[6];
    const float* ln1_b      = (const float*)d_in[7];
    const float* ln2_w      = (const float*)d_in[8];
    const float* ln2_b      = (const float*)d_in[9];
    const float* ff1_w      = (const float*)d_in[10];
    const float* ff1_b      = (const float*)d_in[11];
    const float* ff2_w      = (const float*)d_in[12];
    const float* ff2_b      = (const float*)d_in[13];
    float* out = (float*)d_out;

    void *p_xpad, *p_z, *p_qkv, *p_o, *p_s2, *p_h, *p_g, *p_y;
    void *p_wqkv, *p_wo, *p_w1, *p_w2;
    cudaGetSymbolAddress(&p_xpad, g_xpad);
    cudaGetSymbolAddress(&p_z,    g_z);
    cudaGetSymbolAddress(&p_qkv,  g_qkv);
    cudaGetSymbolAddress(&p_o,    g_o);
    cudaGetSymbolAddress(&p_s2,   g_s2);
    cudaGetSymbolAddress(&p_h,    g_h);
    cudaGetSymbolAddress(&p_g,    g_g);
    cudaGetSymbolAddress(&p_y,    g_y);
    cudaGetSymbolAddress(&p_wqkv, g_wqkv);
    cudaGetSymbolAddress(&p_wo,   g_wo);
    cudaGetSymbolAddress(&p_w1,   g_w1);
    cudaGetSymbolAddress(&p_w2,   g_w2);

    float* xpad = (float*)p_xpad;
    __nv_bfloat16* z   = (__nv_bfloat16*)p_z;
    __nv_bfloat16* qkv = (__nv_bfloat16*)p_qkv;
    __nv_bfloat16* o_  = (__nv_bfloat16*)p_o;
    float* s2 = (float*)p_s2;
    __nv_bfloat16* h_  = (__nv_bfloat16*)p_h;
    __nv_bfloat16* gbuf = (__nv_bfloat16*)p_g;
    float* y  = (float*)p_y;
    __nv_bfloat16* wqkv = (__nv_bfloat16*)p_wqkv;
    __nv_bfloat16* wo   = (__nv_bfloat16*)p_wo;
    __nv_bfloat16* w1   = (__nv_bfloat16*)p_w1;
    __nv_bfloat16* w2   = (__nv_bfloat16*)p_w2;

    const int M = (int)M_TOT;

    // weight conversions (cheap, every call - deterministic)
    cvt_kernel<<<(768 * 256 + 255) / 256, 256>>>(in_proj_w,  wqkv, 768 * 256);
    cvt_kernel<<<(256 * 256 + 255) / 256, 256>>>(out_proj_w, wo,   256 * 256);
    cvt_kernel<<<(1024 * 256 + 255) / 256, 256>>>(ff1_w,     w1,   1024 * 256);
    cvt_kernel<<<(256 * 1024 + 255) / 256, 256>>>(ff2_w,     w2,   256 * 1024);

    // pad + channels-last transpose
    tin_kernel<<<dim3(7, 8, B_ * HP_), dim3(32, 8)>>>(x, xpad);

    // LN1 (over x+pos)
    ln_kernel<<<(M + 7) / 8, 256>>>(xpad, pos, ln1_w, ln1_b, z, M);

    const int mtiles = (M + 127) / 128;
    // QKV GEMM  (n-tile in x so consecutive CTAs share the A tile in L2)
    gemm_bf16<0><<<dim3(768 / 64, mtiles), 256>>>(z, wqkv, in_proj_b, M, 256, 768,
                                                  qkv, nullptr, nullptr, nullptr);
    // attention
    cudaFuncSetAttribute(attn_kernel, cudaFuncAttributeMaxDynamicSharedMemorySize, 163840);
    attn_kernel<<<NWIN, 256, 163840>>>(qkv, o_);

    // out proj + residual (x+pos)
    gemm_bf16<1><<<dim3(256 / 64, mtiles), 256>>>(o_, wo, out_proj_b, M, 256, 256,
                                                  nullptr, s2, xpad, pos);
    // LN2
    ln_kernel<<<(M + 7) / 8, 256>>>(s2, nullptr, ln2_w, ln2_b, h_, M);

    // FF1 + gelu
    gemm_bf16<2><<<dim3(1024 / 64, mtiles), 256>>>(h_, w1, ff1_b, M, 256, 1024,
                                                   gbuf, nullptr, nullptr, nullptr);
    // FF2 + residual
    gemm_bf16<3><<<dim3(256 / 64, mtiles), 256>>>(gbuf, w2, ff2_b, M, 1024, 256,
                                                  nullptr, y, s2, nullptr);

    // transpose back + crop
    tout_kernel<<<dim3(7, 8, B_ * H_), dim3(32, 8)>>>(y, out);
}

// round 4
// speedup vs baseline: 1.5718x; 1.5718x over previous
#include <cuda_runtime.h>
#include <cuda_bf16.h>
#include <mma.h>
#include <math.h>

using namespace nvcuda;

// ---------------- problem constants ----------------
constexpr int  B_   = 8;
constexpr int  C_   = 256;
constexpr int  H_   = 200;
constexpr int  W_   = 200;
constexpr int  WS_  = 7;
constexpr int  HP_  = 203;
constexpr int  WP_  = 203;
constexpr int  NWH  = 29;
constexpr int  NWW  = 29;
constexpr int  NWIN = B_ * NWH * NWW;              // 6728
constexpr size_t M_TOT = (size_t)B_ * HP_ * WP_;   // 329672 real tokens
constexpr int  MTILES = 2576;                      // ceil(M_TOT/128)
constexpr size_t M_PAD = (size_t)MTILES * 128;     // 329728 (GEMMs run guard-free)

// ---------------- scratch (device globals; zero-initialized) ----------------
__device__ float          g_xpad[M_PAD * 256];
__device__ __nv_bfloat16  g_z   [M_PAD * 256];
__device__ __nv_bfloat16  g_qkv [M_PAD * 768];
__device__ __nv_bfloat16  g_o   [M_PAD * 256];
__device__ float          g_s2  [M_PAD * 256];
__device__ __nv_bfloat16  g_h   [M_PAD * 256];
__device__ __nv_bfloat16  g_g   [M_PAD * 1024];

__device__ __nv_bfloat16  g_wqkv[768 * 256];
__device__ __nv_bfloat16  g_wo  [256 * 256];
__device__ __nv_bfloat16  g_w1  [1024 * 256];
__device__ __nv_bfloat16  g_w2  [256 * 1024];

// ---------------- cp.async helpers ----------------
__device__ __forceinline__ void cp16(void* s, const void* g) {
    unsigned sa = (unsigned)__cvta_generic_to_shared(s);
    asm volatile("cp.async.cg.shared.global [%0], [%1], 16;\n" :: "r"(sa), "l"(g));
}
__device__ __forceinline__ void cp_commit() { asm volatile("cp.async.commit_group;\n"); }
__device__ __forceinline__ void cp_wait1()  { asm volatile("cp.async.wait_group 1;\n"); }
__device__ __forceinline__ void cp_wait0()  { asm volatile("cp.async.wait_group 0;\n"); }

// ---------------- fused fp32 -> bf16 weight convert (all 4 weights) ----------------
__global__ void cvt_all_kernel(const float* __restrict__ a0, const float* __restrict__ a1,
                               const float* __restrict__ a2, const float* __restrict__ a3,
                               __nv_bfloat16* __restrict__ o0, __nv_bfloat16* __restrict__ o1,
                               __nv_bfloat16* __restrict__ o2, __nv_bfloat16* __restrict__ o3) {
    int i = blockIdx.x * 256 + threadIdx.x;
    if (i < 196608)       o0[i] = __float2bfloat16(a0[i]);
    else if (i < 262144)  o1[i - 196608] = __float2bfloat16(a1[i - 196608]);
    else if (i < 524288)  o2[i - 262144] = __float2bfloat16(a2[i - 262144]);
    else if (i < 786432)  o3[i - 524288] = __float2bfloat16(a3[i - 524288]);
}

// ---------------- fused NCHW->channels-last pad transpose + LN1 ----------------
__global__ void __launch_bounds__(256) lnin_kernel(
    const float* __restrict__ x, const float* __restrict__ pos,
    const float* __restrict__ gw, const float* __restrict__ gb,
    float* __restrict__ xpad, __nv_bfloat16* __restrict__ z)
{
    __shared__ float tile[256][33];
    const int tx = threadIdx.x, ty = threadIdx.y;
    const int h = blockIdx.y, b = blockIdx.z;
    const int w = blockIdx.x * 32 + tx;
    const bool hv = h < H_;
    const bool wv = w < W_;
#pragma unroll
    for (int j = 0; j < 32; j++) {
        int c = ty + 8 * j;
        float v = 0.f;
        if (hv && wv) v = x[(((size_t)b * 256 + c) * 200 + h) * 200 + w];
        tile[c][tx] = v;
    }
    __syncthreads();

    const int lane = tx;
    for (int tk = ty; tk < 32; tk += 8) {
        int wtok = blockIdx.x * 32 + tk;
        if (wtok >= WP_) break;
        size_t m = ((size_t)(b * HP_ + h)) * WP_ + wtok;
        int t = (h % WS_) * WS_ + (wtok % WS_);
        float v[8];
        float s = 0.f, sq = 0.f;
#pragma unroll
        for (int i = 0; i < 8; i++) {
            int c = lane + 32 * i;
            float xv = tile[c][tk];
            xpad[m * 256 + c] = xv;
            float vv = xv + pos[(size_t)t * 256 + c];
            v[i] = vv;
            s += vv; sq += vv * vv;
        }
#pragma unroll
        for (int o = 16; o; o >>= 1) {
            s  += __shfl_xor_sync(0xffffffffu, s,  o);
            sq += __shfl_xor_sync(0xffffffffu, sq, o);
        }
        float mean = s * (1.f / 256.f);
        float var  = sq * (1.f / 256.f) - mean * mean;
        float inv  = rsqrtf(var + 1e-5f);
#pragma unroll
        for (int i = 0; i < 8; i++) {
            int c = lane + 32 * i;
            z[m * 256 + c] = __float2bfloat16((v[i] - mean) * inv * gw[c] + gb[c]);
        }
    }
}

// ---------------- LayerNorm (LN2): one warp per token ----------------
__global__ void __launch_bounds__(256) ln_kernel(
    const float* __restrict__ in,
    const float* __restrict__ gw, const float* __restrict__ gb,
    __nv_bfloat16* __restrict__ out, int M)
{
    int m = blockIdx.x * 8 + (threadIdx.x >> 5);
    int lane = threadIdx.x & 31;
    if (m >= M) return;
    size_t base = (size_t)m * 256 + lane * 8;
    float4 a0 = *(const float4*)(in + base);
    float4 a1 = *(const float4*)(in + base + 4);
    float v[8] = {a0.x, a0.y, a0.z, a0.w, a1.x, a1.y, a1.z, a1.w};
    float s = 0.f, sq = 0.f;
#pragma unroll
    for (int i = 0; i < 8; i++) { s += v[i]; sq += v[i] * v[i]; }
#pragma unroll
    for (int o = 16; o; o >>= 1) {
        s  += __shfl_xor_sync(0xffffffffu, s,  o);
        sq += __shfl_xor_sync(0xffffffffu, sq, o);
    }
    float mean = s * (1.f / 256.f);
    float var  = sq * (1.f / 256.f) - mean * mean;
    float inv  = rsqrtf(var + 1e-5f);
    float4 w0 = *(const float4*)(gw + lane * 8);
    float4 w1 = *(const float4*)(gw + lane * 8 + 4);
    float4 b0 = *(const float4*)(gb + lane * 8);
    float4 b1 = *(const float4*)(gb + lane * 8 + 4);
    float wv[8] = {w0.x, w0.y, w0.z, w0.w, w1.x, w1.y, w1.z, w1.w};
    float bv[8] = {b0.x, b0.y, b0.z, b0.w, b1.x, b1.y, b1.z, b1.w};
    union { uint4 u; __nv_bfloat16 h[8]; } pk;
#pragma unroll
    for (int i = 0; i < 8; i++)
        pk.h[i] = __float2bfloat16((v[i] - mean) * inv * wv[i] + bv[i]);
    *(uint4*)(out + base) = pk.u;
}

// ---------------- pipelined bf16 GEMM  C = A(MxK) * W(NxK)^T,  M padded (guard-free) -----
constexpr int STAGE_B = 20480;
constexpr int GEMM_SMEM = 128 * 132 * 4;  // 67584 >= 3*STAGE_B=61440

template <int EPI>
__global__ void __launch_bounds__(256) gemm2(
    const __nv_bfloat16* __restrict__ A, const __nv_bfloat16* __restrict__ Wt,
    const float* __restrict__ bias, int K, int NOUT,
    __nv_bfloat16* __restrict__ outb, float* __restrict__ outf,
    const float* __restrict__ resid, const float* __restrict__ pos)
{
    extern __shared__ char sm[];
    const int tid = threadIdx.x;
    const int n0 = blockIdx.x * 128;
    const size_t m0 = (size_t)blockIdx.y * 128;
    const int wid = tid >> 5, wm = wid >> 1, wn = wid & 1;

    const __nv_bfloat16* gA = A + m0 * K;
    const __nv_bfloat16* gB = Wt + (size_t)n0 * K;

    const int r_ld0 = tid >> 2,         g_ld0 = (tid & 3) * 8;
    const int r_ld1 = (tid + 256) >> 2, g_ld1 = g_ld0;

    auto load_stage = [&](int kt, int st) {
        char* base = sm + st * STAGE_B;
        cp16(base + (r_ld0 * 40 + g_ld0) * 2,          gA + (size_t)r_ld0 * K + kt * 32 + g_ld0);
        cp16(base + (r_ld1 * 40 + g_ld1) * 2,          gA + (size_t)r_ld1 * K + kt * 32 + g_ld1);
        cp16(base + 10240 + (r_ld0 * 40 + g_ld0) * 2,  gB + (size_t)r_ld0 * K + kt * 32 + g_ld0);
        cp16(base + 10240 + (r_ld1 * 40 + g_ld1) * 2,  gB + (size_t)r_ld1 * K + kt * 32 + g_ld1);
        cp_commit();
    };

    wmma::fragment<wmma::accumulator, 16, 16, 16, float> acc[2][4];
#pragma unroll
    for (int mi = 0; mi < 2; mi++)
#pragma unroll
        for (int ni = 0; ni < 4; ni++)
            wmma::fill_fragment(acc[mi][ni], 0.f);

    const int KT = K / 32;
    load_stage(0, 0);
    load_stage(1, 1);

    for (int kt = 0; kt < KT; kt++) {
        // always commit exactly one group per iteration (empty on tail) so
        // wait_group 1 provably retires stage kt's fill before compute
        if (kt + 2 < KT) load_stage(kt + 2, (kt + 2) % 3);
        else             cp_commit();
        cp_wait1();
        __syncthreads();
        int st = kt % 3;
        const __nv_bfloat16* a_base = (const __nv_bfloat16*)(sm + st * STAGE_B);
        const __nv_bfloat16* b_base = (const __nv_bfloat16*)(sm + st * STAGE_B + 10240);
#pragma unroll
        for (int kk = 0; kk < 32; kk += 16) {
            wmma::fragment<wmma::matrix_a, 16, 16, 16, __nv_bfloat16, wmma::row_major> af[2];
#pragma unroll
            for (int mi = 0; mi < 2; mi++)
                wmma::load_matrix_sync(af[mi], a_base + (wm * 32 + mi * 16) * 40 + kk, 40);
#pragma unroll
            for (int ni = 0; ni < 4; ni++) {
                wmma::fragment<wmma::matrix_b, 16, 16, 16, __nv_bfloat16, wmma::col_major> bf;
                wmma::load_matrix_sync(bf, b_base + (wn * 64 + ni * 16) * 40 + kk, 40);
#pragma unroll
                for (int mi = 0; mi < 2; mi++)
                    wmma::mma_sync(acc[mi][ni], af[mi], bf, acc[mi][ni]);
            }
        }
        __syncthreads();
    }
    cp_wait0();
    __syncthreads();

    float* Cs = (float*)sm;   // 128 x 132
#pragma unroll
    for (int mi = 0; mi < 2; mi++)
#pragma unroll
        for (int ni = 0; ni < 4; ni++)
            wmma::store_matrix_sync(Cs + (size_t)(wm * 32 + mi * 16) * 132 + wn * 64 + ni * 16,
                                    acc[mi][ni], 132, wmma::mem_row_major);
    __syncthreads();

    // ---------- epilogues ----------
    const int r0 = tid >> 5;
    const int cb = (tid & 31) * 4;
    float4 b4 = *(const float4*)(bias + n0 + cb);

    if (EPI == 0) {
        const float scale = (n0 < 256) ? 0.17677669529663689f : 1.f;
#pragma unroll
        for (int j = 0; j < 16; j++) {
            int r = r0 + j * 8;
            size_t m = m0 + r;
            float4 v = *(const float4*)(Cs + r * 132 + cb);
            v.x = (v.x + b4.x) * scale; v.y = (v.y + b4.y) * scale;
            v.z = (v.z + b4.z) * scale; v.w = (v.w + b4.w) * scale;
            __nv_bfloat162 h0 = __floats2bfloat162_rn(v.x, v.y);
            __nv_bfloat162 h1 = __floats2bfloat162_rn(v.z, v.w);
            uint2 pk; pk.x = *(unsigned*)&h0; pk.y = *(unsigned*)&h1;
            *(uint2*)(outb + m * NOUT + n0 + cb) = pk;
        }
    } else if (EPI == 1) {
#pragma unroll
        for (int j = 0; j < 16; j++) {
            int r = r0 + j * 8;
            size_t m = m0 + r;
            int iw = (int)(m % WP_);
            size_t q = m / WP_;
            int ih = (int)(q % HP_);
            int t = (ih % WS_) * WS_ + (iw % WS_);
            float4 v = *(const float4*)(Cs + r * 132 + cb);
            float4 rs = *(const float4*)(resid + m * 256 + n0 + cb);
            float4 pe = *(const float4*)(pos + (size_t)t * 256 + n0 + cb);
            v.x += b4.x + rs.x + pe.x; v.y += b4.y + rs.y + pe.y;
            v.z += b4.z + rs.z + pe.z; v.w += b4.w + rs.w + pe.w;
            *(float4*)(outf + m * 256 + n0 + cb) = v;
        }
    } else if (EPI == 2) {
#pragma unroll
        for (int j = 0; j < 16; j++) {
            int r = r0 + j * 8;
            size_t m = m0 + r;
            float4 v = *(const float4*)(Cs + r * 132 + cb);
            v.x += b4.x; v.y += b4.y; v.z += b4.z; v.w += b4.w;
            v.x = 0.5f * v.x * (1.f + erff(v.x * 0.7071067811865475f));
            v.y = 0.5f * v.y * (1.f + erff(v.y * 0.7071067811865475f));
            v.z = 0.5f * v.z * (1.f + erff(v.z * 0.7071067811865475f));
            v.w = 0.5f * v.w * (1.f + erff(v.w * 0.7071067811865475f));
            __nv_bfloat162 h0 = __floats2bfloat162_rn(v.x, v.y);
            __nv_bfloat162 h1 = __floats2bfloat162_rn(v.z, v.w);
            uint2 pk; pk.x = *(unsigned*)&h0; pk.y = *(unsigned*)&h1;
            *(uint2*)(outb + m * NOUT + n0 + cb) = pk;
        }
    } else {
#pragma unroll
        for (int j = 0; j < 16; j++) {
            int r = r0 + j * 8;
            size_t m = m0 + r;
            float4 v = *(const float4*)(Cs + r * 132 + cb);
            float4 rs = *(const float4*)(resid + m * 256 + n0 + cb);
            v.x += b4.x + rs.x; v.y += b4.y + rs.y;
            v.z += b4.z + rs.z; v.w += b4.w + rs.w;
            *(float4*)(Cs + r * 132 + cb) = v;
        }
        __syncthreads();
        int tok = tid & 127;
        int sel = tid >> 7;
        size_t m = m0 + tok;
        int iw = (int)(m % WP_);
        size_t q = m / WP_;
        int ih = (int)(q % HP_);
        int b = (int)(q / HP_);
        if (b < B_ && ih < H_ && iw < W_) {
            size_t base = (size_t)b * (256 * 200 * 200) + (size_t)ih * 200 + iw;
            for (int ci = sel; ci < 128; ci += 2)
                outf[base + (size_t)(n0 + ci) * 40000] = Cs[tok * 132 + ci];
        }
    }
}

// ---------------- windowed attention: 1 CTA / window, 1 warp / head ----------------
// Compact per-head layout: 49 real rows, stride 49*32. Rows 49..63 of head h
// alias head h+1's rows 0..14 — FINITE garbage that is multiplied by P==0
// (softmax masks cols >= 49 so P cols 49..63 are exact bf16 zeros). Only head
// 7's rows 49..63 land in the uninit 480-element tail, which we zero (NaN-safe).
// ROUND-2 BUG FIXED HERE: the old code zeroed rows 49..63 of EVERY head,
// which clobbered heads 1..7's real V rows 0..14.
constexpr int HEAD_STRIDE = 49 * 32;                        // 1568 bf16 per head
constexpr int QKV_ELEMS   = 3 * 8 * HEAD_STRIDE + 15 * 32;  // + V tail pad
constexpr int ATTN_SMEM   = QKV_ELEMS * 2 + 8 * 16 * 64 * 4; // 108992 B -> 2 CTA/SM

__global__ void __launch_bounds__(256) attn_kernel(
    const __nv_bfloat16* __restrict__ qkv, __nv_bfloat16* __restrict__ og)
{
    extern __shared__ char smem[];
    __nv_bfloat16* q_s = (__nv_bfloat16*)smem;
    __nv_bfloat16* k_s = q_s + 8 * HEAD_STRIDE;
    __nv_bfloat16* v_s = k_s + 8 * HEAD_STRIDE;
    float* s_base = (float*)(smem + QKV_ELEMS * 2);

    const int win = blockIdx.x;
    const int b = win / (NWH * NWW);
    const int r = win % (NWH * NWW);
    const int wh = r / NWW, ww = r % NWW;
    const int tid = threadIdx.x;

    // gather 49 qkv rows into per-head compact smem
    for (int i = tid; i < 49 * 96; i += 256) {
        int t = i / 96, ch = i % 96;
        int c0 = ch * 8;
        int ih = wh * WS_ + t / WS_, iw = ww * WS_ + t % WS_;
        size_t row = ((size_t)(b * HP_ + ih)) * WP_ + iw;
        uint4 val = *(const uint4*)(qkv + row * 768 + c0);
        int which = c0 >> 8;
        int cl = c0 & 255;
        int head = cl >> 5, d = cl & 31;
        __nv_bfloat16* base = (which == 0) ? q_s : (which == 1) ? k_s : v_s;
        *(uint4*)(base + head * HEAD_STRIDE + t * 32 + d) = val;
    }
    // zero ONLY the 480-element tail (head 7's V rows 49..63); disjoint from
    // all gathered data, so no intra-phase write conflicts.
    for (int i = tid; i < 60; i += 256)
        *(uint4*)(v_s + 8 * HEAD_STRIDE + i * 8) = make_uint4(0, 0, 0, 0);
    __syncthreads();

    const int warp = tid >> 5, lane = tid & 31;
    const __nv_bfloat16* qh = q_s + warp * HEAD_STRIDE;
    const __nv_bfloat16* kh = k_s + warp * HEAD_STRIDE;
    const __nv_bfloat16* vh = v_s + warp * HEAD_STRIDE;
    float*         sw = s_base + warp * 1024;                 // 16x64 fp32
    __nv_bfloat16* pw = (__nv_bfloat16*)sw;                   // 16x64 bf16 (aliased: P row r overwrites S row r/2, already consumed)
    float*         ow = (float*)((char*)sw + 2048);           // 16x32 fp32 (aliased over S rows 8..15, consumed before O store)

    for (int rt = 0; rt < 4; rt++) {
        // S = Q(16x32) * K^T  -> 16x64
        wmma::fragment<wmma::accumulator, 16, 16, 16, float> acc[4];
#pragma unroll
        for (int ct = 0; ct < 4; ct++) wmma::fill_fragment(acc[ct], 0.f);
#pragma unroll
        for (int kk = 0; kk < 32; kk += 16) {
            wmma::fragment<wmma::matrix_a, 16, 16, 16, __nv_bfloat16, wmma::row_major> af;
            wmma::load_matrix_sync(af, qh + (rt * 16) * 32 + kk, 32);
#pragma unroll
            for (int ct = 0; ct < 4; ct++) {
                wmma::fragment<wmma::matrix_b, 16, 16, 16, __nv_bfloat16, wmma::col_major> bf;
                wmma::load_matrix_sync(bf, kh + (ct * 16) * 32 + kk, 32);
                wmma::mma_sync(acc[ct], af, bf, acc[ct]);
            }
        }
#pragma unroll
        for (int ct = 0; ct < 4; ct++)
            wmma::store_matrix_sync(sw + ct * 16, acc[ct], 64, wmma::mem_row_major);
        __syncwarp();

        // row softmax over 49 valid cols; write P (bf16) aliased over S
        for (int rr2 = 0; rr2 < 16; rr2++) {
            float v0 = sw[rr2 * 64 + lane];
            float v1 = (lane < 17) ? sw[rr2 * 64 + lane + 32] : -1e30f;
            float mx = fmaxf(v0, v1);
#pragma unroll
            for (int o = 16; o; o >>= 1) mx = fmaxf(mx, __shfl_xor_sync(0xffffffffu, mx, o));
            float e0 = __expf(v0 - mx);
            float e1 = (lane < 17) ? __expf(v1 - mx) : 0.f;
            float smv = e0 + e1;
#pragma unroll
            for (int o = 16; o; o >>= 1) smv += __shfl_xor_sync(0xffffffffu, smv, o);
            float inv = 1.f / smv;
            __syncwarp();
            pw[rr2 * 64 + lane]      = __float2bfloat16(e0 * inv);
            pw[rr2 * 64 + lane + 32] = __float2bfloat16(e1 * inv);
        }
        __syncwarp();

        // O = P(16x64) * V(64x32)
        wmma::fragment<wmma::accumulator, 16, 16, 16, float> acc2[2];
        wmma::fill_fragment(acc2[0], 0.f);
        wmma::fill_fragment(acc2[1], 0.f);
#pragma unroll
        for (int kk = 0; kk < 4; kk++) {
            wmma::fragment<wmma::matrix_a, 16, 16, 16, __nv_bfloat16, wmma::row_major> pf;
            wmma::load_matrix_sync(pf, pw + kk * 16, 64);
#pragma unroll
            for (int ni = 0; ni < 2; ni++) {
                wmma::fragment<wmma::matrix_b, 16, 16, 16, __nv_bfloat16, wmma::row_major> vf;
                wmma::load_matrix_sync(vf, vh + (kk * 16) * 32 + ni * 16, 32);
                wmma::mma_sync(acc2[ni], pf, vf, acc2[ni]);
            }
        }
        wmma::store_matrix_sync(ow, acc2[0], 32, wmma::mem_row_major);
        wmma::store_matrix_sync(ow + 16, acc2[1], 32, wmma::mem_row_major);
        __syncwarp();

        for (int rr2 = 0; rr2 < 16; rr2++) {
            int t = rt * 16 + rr2;
            if (t >= 49) break;
            int ih = wh * WS_ + t / WS_, iw = ww * WS_ + t % WS_;
            size_t row = ((size_t)(b * HP_ + ih)) * WP_ + iw;
            og[row * 256 + warp * 32 + lane] = __float2bfloat16(ow[rr2 * 32 + lane]);
        }
        __syncwarp();
    }
}

// ---------------- launch ----------------
extern "C" void kernel_launch(void* const* d_in, const int* in_sizes, int n_in,
                              void* d_out, int out_size)
{
    const float* x          = (const float*)d_in[0];
    const float* pos        = (const float*)d_in[1];
    const float* in_proj_w  = (const float*)d_in[2];
    const float* in_proj_b  = (const float*)d_in[3];
    const float* out_proj_w = (const float*)d_in[4];
    const float* out_proj_b = (const float*)d_in[5];
    const float* ln1_w      = (const float*)d_in[6];
    const float* ln1_b      = (const float*)d_in[7];
    const float* ln2_w      = (const float*)d_in[8];
    const float* ln2_b      = (const float*)d_in[9];
    const float* ff1_w      = (const float*)d_in[10];
    const float* ff1_b      = (const float*)d_in[11];
    const float* ff2_w      = (const float*)d_in[12];
    const float* ff2_b      = (const float*)d_in[13];
    float* out = (float*)d_out;

    void *p_xpad, *p_z, *p_qkv, *p_o, *p_s2, *p_h, *p_g;
    void *p_wqkv, *p_wo, *p_w1, *p_w2;
    cudaGetSymbolAddress(&p_xpad, g_xpad);
    cudaGetSymbolAddress(&p_z,    g_z);
    cudaGetSymbolAddress(&p_qkv,  g_qkv);
    cudaGetSymbolAddress(&p_o,    g_o);
    cudaGetSymbolAddress(&p_s2,   g_s2);
    cudaGetSymbolAddress(&p_h,    g_h);
    cudaGetSymbolAddress(&p_g,    g_g);
    cudaGetSymbolAddress(&p_wqkv, g_wqkv);
    cudaGetSymbolAddress(&p_wo,   g_wo);
    cudaGetSymbolAddress(&p_w1,   g_w1);
    cudaGetSymbolAddress(&p_w2,   g_w2);

    float* xpad = (float*)p_xpad;
    __nv_bfloat16* z    = (__nv_bfloat16*)p_z;
    __nv_bfloat16* qkv  = (__nv_bfloat16*)p_qkv;
    __nv_bfloat16* o_   = (__nv_bfloat16*)p_o;
    float* s2 = (float*)p_s2;
    __nv_bfloat16* h_   = (__nv_bfloat16*)p_h;
    __nv_bfloat16* gbuf = (__nv_bfloat16*)p_g;
    __nv_bfloat16* wqkv = (__nv_bfloat16*)p_wqkv;
    __nv_bfloat16* wo   = (__nv_bfloat16*)p_wo;
    __nv_bfloat16* w1   = (__nv_bfloat16*)p_w1;
    __nv_bfloat16* w2   = (__nv_bfloat16*)p_w2;

    cudaFuncSetAttribute(gemm2<0>, cudaFuncAttributeMaxDynamicSharedMemorySize, GEMM_SMEM);
    cudaFuncSetAttribute(gemm2<1>, cudaFuncAttributeMaxDynamicSharedMemorySize, GEMM_SMEM);
    cudaFuncSetAttribute(gemm2<2>, cudaFuncAttributeMaxDynamicSharedMemorySize, GEMM_SMEM);
    cudaFuncSetAttribute(gemm2<3>, cudaFuncAttributeMaxDynamicSharedMemorySize, GEMM_SMEM);
    cudaFuncSetAttribute(attn_kernel, cudaFuncAttributeMaxDynamicSharedMemorySize, ATTN_SMEM);

    // weights -> bf16
    cvt_all_kernel<<<3072, 256>>>(in_proj_w, out_proj_w, ff1_w, ff2_w, wqkv, wo, w1, w2);

    // fused pad-transpose + LN1
    lnin_kernel<<<dim3(7, HP_, B_), dim3(32, 8)>>>(x, pos, ln1_w, ln1_b, xpad, z);

    // QKV GEMM
    gemm2<0><<<dim3(6, MTILES), 256, GEMM_SMEM>>>(z, wqkv, in_proj_b, 256, 768,
                                                  qkv, nullptr, nullptr, nullptr);
    // attention
    attn_kernel<<<NWIN, 256, ATTN_SMEM>>>(qkv, o_);

    // out proj + residual(x+pos) -> s2
    gemm2<1><<<dim3(2, MTILES), 256, GEMM_SMEM>>>(o_, wo, out_proj_b, 256, 256,
                                                  nullptr, s2, xpad, pos);
    // LN2
    ln_kernel<<<((int)M_TOT + 7) / 8, 256>>>(s2, ln2_w, ln2_b, h_, (int)M_TOT);

    // FF1 + gelu
    gemm2<2><<<dim3(8, MTILES), 256, GEMM_SMEM>>>(h_, w1, ff1_b, 256, 1024,
                                                  gbuf, nullptr, nullptr, nullptr);
    // FF2 + residual -> direct NCHW cropped output
    gemm2<3><<<dim3(2, MTILES), 256, GEMM_SMEM>>>(gbuf, w2, ff2_b, 1024, 256,
                                                  nullptr, out, s2, nullptr);
}

// round 5
// speedup vs baseline: 2.0772x; 1.3216x over previous
#include <cuda_runtime.h>
#include <cuda_bf16.h>
#include <mma.h>
#include <math.h>

using namespace nvcuda;

// ---------------- problem constants ----------------
constexpr int  B_   = 8;
constexpr int  C_   = 256;
constexpr int  H_   = 200;
constexpr int  W_   = 200;
constexpr int  WS_  = 7;
constexpr int  HP_  = 203;
constexpr int  WP_  = 203;
constexpr int  NWH  = 29;
constexpr int  NWW  = 29;
constexpr int  NWIN = B_ * NWH * NWW;              // 6728
constexpr size_t M_TOT = (size_t)B_ * HP_ * WP_;   // 329672 real tokens
constexpr int  MTILES = 2576;                      // ceil(M_TOT/128)
constexpr size_t M_PAD = (size_t)MTILES * 128;     // 329728 (GEMMs run guard-free)

// ---------------- scratch (device globals; zero-initialized) ----------------
__device__ float          g_xpad[M_PAD * 256];
__device__ __nv_bfloat16  g_z   [M_PAD * 256];
__device__ __nv_bfloat16  g_qkv [M_PAD * 768];
__device__ __nv_bfloat16  g_o   [M_PAD * 256];
__device__ float          g_s2  [M_PAD * 256];
__device__ __nv_bfloat16  g_h   [M_PAD * 256];
__device__ __nv_bfloat16  g_g   [M_PAD * 1024];

__device__ __nv_bfloat16  g_wqkv[768 * 256];
__device__ __nv_bfloat16  g_wo  [256 * 256];
__device__ __nv_bfloat16  g_w1  [1024 * 256];
__device__ __nv_bfloat16  g_w2  [256 * 1024];

// ---------------- cp.async helpers ----------------
__device__ __forceinline__ void cp16(void* s, const void* g) {
    unsigned sa = (unsigned)__cvta_generic_to_shared(s);
    asm volatile("cp.async.cg.shared.global [%0], [%1], 16;\n" :: "r"(sa), "l"(g));
}
__device__ __forceinline__ void cp_commit() { asm volatile("cp.async.commit_group;\n"); }
__device__ __forceinline__ void cp_wait1()  { asm volatile("cp.async.wait_group 1;\n"); }
__device__ __forceinline__ void cp_wait0()  { asm volatile("cp.async.wait_group 0;\n"); }

// raw bf16 mma with ISA-defined fragment layout (m16n8k16, f32 accum)
__device__ __forceinline__ void mma16816(float* d,
                                         unsigned a0, unsigned a1, unsigned a2, unsigned a3,
                                         unsigned b0, unsigned b1) {
    asm volatile("mma.sync.aligned.m16n8k16.row.col.f32.bf16.bf16.f32 "
                 "{%0,%1,%2,%3}, {%4,%5,%6,%7}, {%8,%9}, {%0,%1,%2,%3};"
                 : "+f"(d[0]), "+f"(d[1]), "+f"(d[2]), "+f"(d[3])
                 : "r"(a0), "r"(a1), "r"(a2), "r"(a3), "r"(b0), "r"(b1));
}

// ---------------- fused fp32 -> bf16 weight convert (all 4 weights) ----------------
__global__ void cvt_all_kernel(const float* __restrict__ a0, const float* __restrict__ a1,
                               const float* __restrict__ a2, const float* __restrict__ a3,
                               __nv_bfloat16* __restrict__ o0, __nv_bfloat16* __restrict__ o1,
                               __nv_bfloat16* __restrict__ o2, __nv_bfloat16* __restrict__ o3) {
    int i = blockIdx.x * 256 + threadIdx.x;
    if (i < 196608)       o0[i] = __float2bfloat16(a0[i]);
    else if (i < 262144)  o1[i - 196608] = __float2bfloat16(a1[i - 196608]);
    else if (i < 524288)  o2[i - 262144] = __float2bfloat16(a2[i - 262144]);
    else if (i < 786432)  o3[i - 524288] = __float2bfloat16(a3[i - 524288]);
}

// ---------------- fused NCHW->channels-last pad transpose + LN1 ----------------
__global__ void __launch_bounds__(256) lnin_kernel(
    const float* __restrict__ x, const float* __restrict__ pos,
    const float* __restrict__ gw, const float* __restrict__ gb,
    float* __restrict__ xpad, __nv_bfloat16* __restrict__ z)
{
    __shared__ float tile[256][33];
    const int tx = threadIdx.x, ty = threadIdx.y;
    const int h = blockIdx.y, b = blockIdx.z;
    const int w = blockIdx.x * 32 + tx;
    const bool hv = h < H_;
    const bool wv = w < W_;
#pragma unroll
    for (int j = 0; j < 32; j++) {
        int c = ty + 8 * j;
        float v = 0.f;
        if (hv && wv) v = x[(((size_t)b * 256 + c) * 200 + h) * 200 + w];
        tile[c][tx] = v;
    }
    __syncthreads();

    const int lane = tx;
    for (int tk = ty; tk < 32; tk += 8) {
        int wtok = blockIdx.x * 32 + tk;
        if (wtok >= WP_) break;
        size_t m = ((size_t)(b * HP_ + h)) * WP_ + wtok;
        int t = (h % WS_) * WS_ + (wtok % WS_);
        float v[8];
        float s = 0.f, sq = 0.f;
#pragma unroll
        for (int i = 0; i < 8; i++) {
            int c = lane + 32 * i;
            float xv = tile[c][tk];
            xpad[m * 256 + c] = xv;
            float vv = xv + pos[(size_t)t * 256 + c];
            v[i] = vv;
            s += vv; sq += vv * vv;
        }
#pragma unroll
        for (int o = 16; o; o >>= 1) {
            s  += __shfl_xor_sync(0xffffffffu, s,  o);
            sq += __shfl_xor_sync(0xffffffffu, sq, o);
        }
        float mean = s * (1.f / 256.f);
        float var  = sq * (1.f / 256.f) - mean * mean;
        float inv  = rsqrtf(var + 1e-5f);
#pragma unroll
        for (int i = 0; i < 8; i++) {
            int c = lane + 32 * i;
            z[m * 256 + c] = __float2bfloat16((v[i] - mean) * inv * gw[c] + gb[c]);
        }
    }
}

// ---------------- LayerNorm (LN2): one warp per token ----------------
__global__ void __launch_bounds__(256) ln_kernel(
    const float* __restrict__ in,
    const float* __restrict__ gw, const float* __restrict__ gb,
    __nv_bfloat16* __restrict__ out, int M)
{
    int m = blockIdx.x * 8 + (threadIdx.x >> 5);
    int lane = threadIdx.x & 31;
    if (m >= M) return;
    size_t base = (size_t)m * 256 + lane * 8;
    float4 a0 = *(const float4*)(in + base);
    float4 a1 = *(const float4*)(in + base + 4);
    float v[8] = {a0.x, a0.y, a0.z, a0.w, a1.x, a1.y, a1.z, a1.w};
    float s = 0.f, sq = 0.f;
#pragma unroll
    for (int i = 0; i < 8; i++) { s += v[i]; sq += v[i] * v[i]; }
#pragma unroll
    for (int o = 16; o; o >>= 1) {
        s  += __shfl_xor_sync(0xffffffffu, s,  o);
        sq += __shfl_xor_sync(0xffffffffu, sq, o);
    }
    float mean = s * (1.f / 256.f);
    float var  = sq * (1.f / 256.f) - mean * mean;
    float inv  = rsqrtf(var + 1e-5f);
    float4 w0 = *(const float4*)(gw + lane * 8);
    float4 w1 = *(const float4*)(gw + lane * 8 + 4);
    float4 b0 = *(const float4*)(gb + lane * 8);
    float4 b1 = *(const float4*)(gb + lane * 8 + 4);
    float wv[8] = {w0.x, w0.y, w0.z, w0.w, w1.x, w1.y, w1.z, w1.w};
    float bv[8] = {b0.x, b0.y, b0.z, b0.w, b1.x, b1.y, b1.z, b1.w};
    union { uint4 u; __nv_bfloat16 h[8]; } pk;
#pragma unroll
    for (int i = 0; i < 8; i++)
        pk.h[i] = __float2bfloat16((v[i] - mean) * inv * wv[i] + bv[i]);
    *(uint4*)(out + base) = pk.u;
}

// ---------------- pipelined bf16 GEMM  C = A(MxK) * W(NxK)^T,  M padded -----
// BM=128, BN=128, BK=64, 3-stage cp.async ring, ONE barrier per K-iter.
constexpr int STAGE_B  = 2 * 128 * 72 * 2;   // 36864 bytes (A tile + B tile)
constexpr int GEMM_SMEM = 3 * STAGE_B;        // 110592; Cs (67584) aliases

template <int EPI>
__global__ void __launch_bounds__(256, 2) gemm2(
    const __nv_bfloat16* __restrict__ A, const __nv_bfloat16* __restrict__ Wt,
    const float* __restrict__ bias, int K, int NOUT,
    __nv_bfloat16* __restrict__ outb, float* __restrict__ outf,
    const float* __restrict__ resid, const float* __restrict__ pos)
{
    extern __shared__ char sm[];
    const int tid = threadIdx.x;
    const int n0 = blockIdx.x * 128;
    const size_t m0 = (size_t)blockIdx.y * 128;
    const int wid = tid >> 5, wm = wid >> 1, wn = wid & 1;

    const __nv_bfloat16* gA = A + m0 * K;
    const __nv_bfloat16* gB = Wt + (size_t)n0 * K;

    auto load_stage = [&](int kt, int st) {
        char* base = sm + st * STAGE_B;
#pragma unroll
        for (int it = 0; it < 4; it++) {
            int idx = tid + it * 256;
            int r = idx >> 3, col = (idx & 7) * 8;
            cp16(base + (r * 72 + col) * 2,         gA + (size_t)r * K + kt * 64 + col);
            cp16(base + 18432 + (r * 72 + col) * 2, gB + (size_t)r * K + kt * 64 + col);
        }
        cp_commit();
    };

    wmma::fragment<wmma::accumulator, 16, 16, 16, float> acc[2][4];
#pragma unroll
    for (int mi = 0; mi < 2; mi++)
#pragma unroll
        for (int ni = 0; ni < 4; ni++)
            wmma::fill_fragment(acc[mi][ni], 0.f);

    const int KT = K / 64;
    load_stage(0, 0);
    load_stage(1, 1);

    for (int kt = 0; kt < KT; kt++) {
        cp_wait1();          // stage kt's fill group retired
        __syncthreads();     // also: all warps done computing stage (kt-1) -> WAR-safe
        // exactly one commit per iteration keeps the wait_group accounting exact
        if (kt + 2 < KT) load_stage(kt + 2, (kt + 2) % 3);
        else             cp_commit();
        const __nv_bfloat16* a_base = (const __nv_bfloat16*)(sm + (kt % 3) * STAGE_B);
        const __nv_bfloat16* b_base = a_base + 128 * 72;
#pragma unroll
        for (int kk = 0; kk < 64; kk += 16) {
            wmma::fragment<wmma::matrix_a, 16, 16, 16, __nv_bfloat16, wmma::row_major> af[2];
#pragma unroll
            for (int mi = 0; mi < 2; mi++)
                wmma::load_matrix_sync(af[mi], a_base + (wm * 32 + mi * 16) * 72 + kk, 72);
#pragma unroll
            for (int ni = 0; ni < 4; ni++) {
                wmma::fragment<wmma::matrix_b, 16, 16, 16, __nv_bfloat16, wmma::col_major> bf;
                wmma::load_matrix_sync(bf, b_base + (wn * 64 + ni * 16) * 72 + kk, 72);
#pragma unroll
                for (int mi = 0; mi < 2; mi++)
                    wmma::mma_sync(acc[mi][ni], af[mi], bf, acc[mi][ni]);
            }
        }
    }
    cp_wait0();
    __syncthreads();

    float* Cs = (float*)sm;   // 128 x 132
#pragma unroll
    for (int mi = 0; mi < 2; mi++)
#pragma unroll
        for (int ni = 0; ni < 4; ni++)
            wmma::store_matrix_sync(Cs + (size_t)(wm * 32 + mi * 16) * 132 + wn * 64 + ni * 16,
                                    acc[mi][ni], 132, wmma::mem_row_major);
    __syncthreads();

    // ---------- epilogues ----------
    const int r0 = tid >> 5;
    const int cb = (tid & 31) * 4;
    float4 b4 = *(const float4*)(bias + n0 + cb);

    if (EPI == 0) {
        const float scale = (n0 < 256) ? 0.17677669529663689f : 1.f;
#pragma unroll
        for (int j = 0; j < 16; j++) {
            int r = r0 + j * 8;
            size_t m = m0 + r;
            float4 v = *(const float4*)(Cs + r * 132 + cb);
            v.x = (v.x + b4.x) * scale; v.y = (v.y + b4.y) * scale;
            v.z = (v.z + b4.z) * scale; v.w = (v.w + b4.w) * scale;
            __nv_bfloat162 h0 = __floats2bfloat162_rn(v.x, v.y);
            __nv_bfloat162 h1 = __floats2bfloat162_rn(v.z, v.w);
            uint2 pk; pk.x = *(unsigned*)&h0; pk.y = *(unsigned*)&h1;
            *(uint2*)(outb + m * NOUT + n0 + cb) = pk;
        }
    } else if (EPI == 1) {
#pragma unroll
        for (int j = 0; j < 16; j++) {
            int r = r0 + j * 8;
            size_t m = m0 + r;
            int iw = (int)(m % WP_);
            size_t q = m / WP_;
            int ih = (int)(q % HP_);
            int t = (ih % WS_) * WS_ + (iw % WS_);
            float4 v = *(const float4*)(Cs + r * 132 + cb);
            float4 rs = *(const float4*)(resid + m * 256 + n0 + cb);
            float4 pe = *(const float4*)(pos + (size_t)t * 256 + n0 + cb);
            v.x += b4.x + rs.x + pe.x; v.y += b4.y + rs.y + pe.y;
            v.z += b4.z + rs.z + pe.z; v.w += b4.w + rs.w + pe.w;
            *(float4*)(outf + m * 256 + n0 + cb) = v;
        }
    } else if (EPI == 2) {
#pragma unroll
        for (int j = 0; j < 16; j++) {
            int r = r0 + j * 8;
            size_t m = m0 + r;
            float4 v = *(const float4*)(Cs + r * 132 + cb);
            v.x += b4.x; v.y += b4.y; v.z += b4.z; v.w += b4.w;
            v.x = 0.5f * v.x * (1.f + erff(v.x * 0.7071067811865475f));
            v.y = 0.5f * v.y * (1.f + erff(v.y * 0.7071067811865475f));
            v.z = 0.5f * v.z * (1.f + erff(v.z * 0.7071067811865475f));
            v.w = 0.5f * v.w * (1.f + erff(v.w * 0.7071067811865475f));
            __nv_bfloat162 h0 = __floats2bfloat162_rn(v.x, v.y);
            __nv_bfloat162 h1 = __floats2bfloat162_rn(v.z, v.w);
            uint2 pk; pk.x = *(unsigned*)&h0; pk.y = *(unsigned*)&h1;
            *(uint2*)(outb + m * NOUT + n0 + cb) = pk;
        }
    } else {
#pragma unroll
        for (int j = 0; j < 16; j++) {
            int r = r0 + j * 8;
            size_t m = m0 + r;
            float4 v = *(const float4*)(Cs + r * 132 + cb);
            float4 rs = *(const float4*)(resid + m * 256 + n0 + cb);
            v.x += b4.x + rs.x; v.y += b4.y + rs.y;
            v.z += b4.z + rs.z; v.w += b4.w + rs.w;
            *(float4*)(Cs + r * 132 + cb) = v;
        }
        __syncthreads();
        int tok = tid & 127;
        int sel = tid >> 7;
        size_t m = m0 + tok;
        int iw = (int)(m % WP_);
        size_t q = m / WP_;
        int ih = (int)(q % HP_);
        int b = (int)(q / HP_);
        if (b < B_ && ih < H_ && iw < W_) {
            size_t base = (size_t)b * (256 * 200 * 200) + (size_t)ih * 200 + iw;
            for (int ci = sel; ci < 128; ci += 2)
                outf[base + (size_t)(n0 + ci) * 40000] = Cs[tok * 132 + ci];
        }
    }
}

// ---------------- windowed attention: register-softmax mma.sync version ---------
// 1 CTA/window, 1 warp/head. Q/K/V in smem (rows padded to 40 bf16 for
// conflict-free 32-bit lane loads); S, softmax, P, O all register-resident
// with ISA-defined m16n8k16 fragment layouts. No score smem at all.
// Head h's rows 49..63 alias head h+1 (finite garbage, masked by softmax);
// only the V tail (15 rows after head 7) must be zeroed for NaN-safety.
constexpr int RPAD     = 40;                    // padded row length (bf16)
constexpr int HSTRIDE  = 49 * RPAD;             // 1960 bf16 per head
constexpr int ATTN_SMEM = (3 * 8 * HSTRIDE + 15 * RPAD) * 2;  // 95280 B -> 2 CTA/SM

__global__ void __launch_bounds__(256, 2) attn_kernel(
    const __nv_bfloat16* __restrict__ qkv, __nv_bfloat16* __restrict__ og)
{
    extern __shared__ char smem[];
    __nv_bfloat16* q_s = (__nv_bfloat16*)smem;
    __nv_bfloat16* k_s = q_s + 8 * HSTRIDE;
    __nv_bfloat16* v_s = k_s + 8 * HSTRIDE;

    const int win = blockIdx.x;
    const int b = win / (NWH * NWW);
    const int r = win % (NWH * NWW);
    const int wh = r / NWW, ww = r % NWW;
    const int tid = threadIdx.x;

    // gather 49 qkv rows into per-head compact padded smem
    for (int i = tid; i < 49 * 96; i += 256) {
        int t = i / 96, ch = i % 96;
        int c0 = ch * 8;
        int ih = wh * WS_ + t / WS_, iw = ww * WS_ + t % WS_;
        size_t row = ((size_t)(b * HP_ + ih)) * WP_ + iw;
        uint4 val = *(const uint4*)(qkv + row * 768 + c0);
        int which = c0 >> 8;
        int cl = c0 & 255;
        int head = cl >> 5, d = cl & 31;
        __nv_bfloat16* base = (which == 0) ? q_s : (which == 1) ? k_s : v_s;
        *(uint4*)(base + head * HSTRIDE + t * RPAD + d) = val;
    }
    // zero the V tail (head 7's aliased rows 49..63): 15*40 = 600 bf16 = 75 uint4
    for (int i = tid; i < 75; i += 256)
        *(uint4*)(v_s + 8 * HSTRIDE + i * 8) = make_uint4(0, 0, 0, 0);
    __syncthreads();

    const int warp = tid >> 5, lane = tid & 31;
    const int g = lane >> 2, c = lane & 3;
    const __nv_bfloat16* qh = q_s + warp * HSTRIDE;
    const __nv_bfloat16* kh = k_s + warp * HSTRIDE;
    const __nv_bfloat16* vh = v_s + warp * HSTRIDE;

    // K fragments, persistent across all 4 row-tiles.
    // B frag for S-mma: B[k=d][n=token]; token row = 8*nt+g, d = 16*kc + 2c (+1), +8
    unsigned kb[8][2][2];
#pragma unroll
    for (int nt = 0; nt < 8; nt++)
#pragma unroll
        for (int kc = 0; kc < 2; kc++) {
            const __nv_bfloat16* kr = kh + (8 * nt + g) * RPAD + 16 * kc + 2 * c;
            kb[nt][kc][0] = *(const unsigned*)kr;
            kb[nt][kc][1] = *(const unsigned*)(kr + 8);
        }

    for (int rt = 0; rt < 4; rt++) {
        // ---- Q fragments for this 16-row tile ----
        unsigned qa[2][4];
#pragma unroll
        for (int kc = 0; kc < 2; kc++) {
            const __nv_bfloat16* q0 = qh + (16 * rt + g) * RPAD + 16 * kc + 2 * c;
            const __nv_bfloat16* q1 = q0 + 8 * RPAD;
            qa[kc][0] = *(const unsigned*)q0;
            qa[kc][1] = *(const unsigned*)q1;
            qa[kc][2] = *(const unsigned*)(q0 + 8);
            qa[kc][3] = *(const unsigned*)(q1 + 8);
        }

        // ---- S = Q * K^T (16 x 64), register accumulators ----
        float sa[8][4];
#pragma unroll
        for (int nt = 0; nt < 8; nt++) { sa[nt][0] = sa[nt][1] = sa[nt][2] = sa[nt][3] = 0.f; }
#pragma unroll
        for (int nt = 0; nt < 8; nt++)
#pragma unroll
            for (int kc = 0; kc < 2; kc++)
                mma16816(sa[nt], qa[kc][0], qa[kc][1], qa[kc][2], qa[kc][3],
                         kb[nt][kc][0], kb[nt][kc][1]);

        // ---- mask cols >= 49 (tiles 6,7 only) ----
#pragma unroll
        for (int nt = 6; nt < 8; nt++) {
            int col0 = 8 * nt + 2 * c;
            if (col0 >= 49)     { sa[nt][0] = -1e30f; sa[nt][2] = -1e30f; }
            if (col0 + 1 >= 49) { sa[nt][1] = -1e30f; sa[nt][3] = -1e30f; }
        }

        // ---- register softmax: rows (16rt+g) and (16rt+g+8) ----
        float mx0 = -1e30f, mx1 = -1e30f;
#pragma unroll
        for (int nt = 0; nt < 8; nt++) {
            mx0 = fmaxf(mx0, fmaxf(sa[nt][0], sa[nt][1]));
            mx1 = fmaxf(mx1, fmaxf(sa[nt][2], sa[nt][3]));
        }
        mx0 = fmaxf(mx0, __shfl_xor_sync(0xffffffffu, mx0, 1));
        mx0 = fmaxf(mx0, __shfl_xor_sync(0xffffffffu, mx0, 2));
        mx1 = fmaxf(mx1, __shfl_xor_sync(0xffffffffu, mx1, 1));
        mx1 = fmaxf(mx1, __shfl_xor_sync(0xffffffffu, mx1, 2));
        float sm0 = 0.f, sm1 = 0.f;
#pragma unroll
        for (int nt = 0; nt < 8; nt++) {
            sa[nt][0] = __expf(sa[nt][0] - mx0); sm0 += sa[nt][0];
            sa[nt][1] = __expf(sa[nt][1] - mx0); sm0 += sa[nt][1];
            sa[nt][2] = __expf(sa[nt][2] - mx1); sm1 += sa[nt][2];
            sa[nt][3] = __expf(sa[nt][3] - mx1); sm1 += sa[nt][3];
        }
        sm0 += __shfl_xor_sync(0xffffffffu, sm0, 1);
        sm0 += __shfl_xor_sync(0xffffffffu, sm0, 2);
        sm1 += __shfl_xor_sync(0xffffffffu, sm1, 1);
        sm1 += __shfl_xor_sync(0xffffffffu, sm1, 2);
        float inv0 = 1.f / sm0, inv1 = 1.f / sm1;

        // ---- pack P into A fragments (pure register remap, no shuffles) ----
        unsigned pa[4][4];
#pragma unroll
        for (int kc = 0; kc < 4; kc++) {
            __nv_bfloat162 t0 = __floats2bfloat162_rn(sa[2 * kc][0] * inv0, sa[2 * kc][1] * inv0);
            __nv_bfloat162 t1 = __floats2bfloat162_rn(sa[2 * kc][2] * inv1, sa[2 * kc][3] * inv1);
            __nv_bfloat162 t2 = __floats2bfloat162_rn(sa[2 * kc + 1][0] * inv0, sa[2 * kc + 1][1] * inv0);
            __nv_bfloat162 t3 = __floats2bfloat162_rn(sa[2 * kc + 1][2] * inv1, sa[2 * kc + 1][3] * inv1);
            pa[kc][0] = *(unsigned*)&t0; pa[kc][1] = *(unsigned*)&t1;
            pa[kc][2] = *(unsigned*)&t2; pa[kc][3] = *(unsigned*)&t3;
        }

        // ---- O = P * V (16 x 32) ----
        float oa[4][4];
#pragma unroll
        for (int nt = 0; nt < 4; nt++) { oa[nt][0] = oa[nt][1] = oa[nt][2] = oa[nt][3] = 0.f; }
#pragma unroll
        for (int kc = 0; kc < 4; kc++)
#pragma unroll
            for (int nt = 0; nt < 4; nt++) {
                // B frag: V[k=token][n=d]; tokens 16kc+2c(+1)(+8), d = 8nt+g
                const unsigned short* vp =
                    (const unsigned short*)(vh + (16 * kc + 2 * c) * RPAD + 8 * nt + g);
                unsigned b0 = (unsigned)vp[0] | ((unsigned)vp[RPAD] << 16);
                unsigned b1 = (unsigned)vp[8 * RPAD] | ((unsigned)vp[9 * RPAD] << 16);
                mma16816(oa[nt], pa[kc][0], pa[kc][1], pa[kc][2], pa[kc][3], b0, b1);
            }

        // ---- store O rows (skip masked rows >= 49) ----
        int t0r = 16 * rt + g, t1r = t0r + 8;
#pragma unroll
        for (int half = 0; half < 2; half++) {
            int t = half ? t1r : t0r;
            if (t < 49) {
                int ih = wh * WS_ + t / WS_, iw = ww * WS_ + t % WS_;
                size_t row = ((size_t)(b * HP_ + ih)) * WP_ + iw;
                __nv_bfloat16* orow = og + row * 256 + warp * 32 + 2 * c;
#pragma unroll
                for (int nt = 0; nt < 4; nt++) {
                    __nv_bfloat162 pk2 = half
                        ? __floats2bfloat162_rn(oa[nt][2], oa[nt][3])
                        : __floats2bfloat162_rn(oa[nt][0], oa[nt][1]);
                    *(unsigned*)(orow + 8 * nt) = *(unsigned*)&pk2;
                }
            }
        }
    }
}

// ---------------- launch ----------------
extern "C" void kernel_launch(void* const* d_in, const int* in_sizes, int n_in,
                              void* d_out, int out_size)
{
    const float* x          = (const float*)d_in[0];
    const float* pos        = (const float*)d_in[1];
    const float* in_proj_w  = (const float*)d_in[2];
    const float* in_proj_b  = (const float*)d_in[3];
    const float* out_proj_w = (const float*)d_in[4];
    const float* out_proj_b = (const float*)d_in[5];
    const float* ln1_w      = (const float*)d_in[6];
    const float* ln1_b      = (const float*)d_in[7];
    const float* ln2_w      = (const float*)d_in[8];
    const float* ln2_b      = (const float*)d_in[9];
    const float* ff1_w      = (const float*)d_in[10];
    const float* ff1_b      = (const float*)d_in[11];
    const float* ff2_w      = (const float*)d_in[12];
    const float* ff2_b      = (const float*)d_in[13];
    float* out = (float*)d_out;

    void *p_xpad, *p_z, *p_qkv, *p_o, *p_s2, *p_h, *p_g;
    void *p_wqkv, *p_wo, *p_w1, *p_w2;
    cudaGetSymbolAddress(&p_xpad, g_xpad);
    cudaGetSymbolAddress(&p_z,    g_z);
    cudaGetSymbolAddress(&p_qkv,  g_qkv);
    cudaGetSymbolAddress(&p_o,    g_o);
    cudaGetSymbolAddress(&p_s2,   g_s2);
    cudaGetSymbolAddress(&p_h,    g_h);
    cudaGetSymbolAddress(&p_g,    g_g);
    cudaGetSymbolAddress(&p_wqkv, g_wqkv);
    cudaGetSymbolAddress(&p_wo,   g_wo);
    cudaGetSymbolAddress(&p_w1,   g_w1);
    cudaGetSymbolAddress(&p_w2,   g_w2);

    float* xpad = (float*)p_xpad;
    __nv_bfloat16* z    = (__nv_bfloat16*)p_z;
    __nv_bfloat16* qkv  = (__nv_bfloat16*)p_qkv;
    __nv_bfloat16* o_   = (__nv_bfloat16*)p_o;
    float* s2 = (float*)p_s2;
    __nv_bfloat16* h_   = (__nv_bfloat16*)p_h;
    __nv_bfloat16* gbuf = (__nv_bfloat16*)p_g;
    __nv_bfloat16* wqkv = (__nv_bfloat16*)p_wqkv;
    __nv_bfloat16* wo   = (__nv_bfloat16*)p_wo;
    __nv_bfloat16* w1   = (__nv_bfloat16*)p_w1;
    __nv_bfloat16* w2   = (__nv_bfloat16*)p_w2;

    cudaFuncSetAttribute(gemm2<0>, cudaFuncAttributeMaxDynamicSharedMemorySize, GEMM_SMEM);
    cudaFuncSetAttribute(gemm2<1>, cudaFuncAttributeMaxDynamicSharedMemorySize, GEMM_SMEM);
    cudaFuncSetAttribute(gemm2<2>, cudaFuncAttributeMaxDynamicSharedMemorySize, GEMM_SMEM);
    cudaFuncSetAttribute(gemm2<3>, cudaFuncAttributeMaxDynamicSharedMemorySize, GEMM_SMEM);
    cudaFuncSetAttribute(attn_kernel, cudaFuncAttributeMaxDynamicSharedMemorySize, ATTN_SMEM);

    // weights -> bf16
    cvt_all_kernel<<<3072, 256>>>(in_proj_w, out_proj_w, ff1_w, ff2_w, wqkv, wo, w1, w2);

    // fused pad-transpose + LN1
    lnin_kernel<<<dim3(7, HP_, B_), dim3(32, 8)>>>(x, pos, ln1_w, ln1_b, xpad, z);

    // QKV GEMM
    gemm2<0><<<dim3(6, MTILES), 256, GEMM_SMEM>>>(z, wqkv, in_proj_b, 256, 768,
                                                  qkv, nullptr, nullptr, nullptr);
    // attention
    attn_kernel<<<NWIN, 256, ATTN_SMEM>>>(qkv, o_);

    // out proj + residual(x+pos) -> s2
    gemm2<1><<<dim3(2, MTILES), 256, GEMM_SMEM>>>(o_, wo, out_proj_b, 256, 256,
                                                  nullptr, s2, xpad, pos);
    // LN2
    ln_kernel<<<((int)M_TOT + 7) / 8, 256>>>(s2, ln2_w, ln2_b, h_, (int)M_TOT);

    // FF1 + gelu
    gemm2<2><<<dim3(8, MTILES), 256, GEMM_SMEM>>>(h_, w1, ff1_b, 256, 1024,
                                                  gbuf, nullptr, nullptr, nullptr);
    // FF2 + residual -> direct NCHW cropped output
    gemm2<3><<<dim3(2, MTILES), 256, GEMM_SMEM>>>(gbuf, w2, ff2_b, 1024, 256,
                                                  nullptr, out, s2, nullptr);
}

// round 8
// speedup vs baseline: 2.1702x; 1.0448x over previous
#include <cuda_runtime.h>
#include <cuda_bf16.h>
#include <cstdint>
#include <math.h>

// ---------------- problem constants ----------------
constexpr int  B_   = 8;
constexpr int  C_   = 256;
constexpr int  H_   = 200;
constexpr int  W_   = 200;
constexpr int  WS_  = 7;
constexpr int  HP_  = 203;
constexpr int  WP_  = 203;
constexpr int  NWH  = 29;
constexpr int  NWW  = 29;
constexpr int  NWIN = B_ * NWH * NWW;              // 6728
constexpr size_t M_TOT = (size_t)B_ * HP_ * WP_;   // 329672 real tokens
constexpr int  MT256  = 1288;                      // M_PAD / 256
constexpr size_t M_PAD = (size_t)MT256 * 256;      // 329728 (GEMMs run guard-free)

// ---------------- scratch (device globals; zero-initialized) ----------------
__device__ float          g_xpad[M_PAD * 256];
__device__ __nv_bfloat16  g_z   [M_PAD * 256];
__device__ __nv_bfloat16  g_qkv [M_PAD * 768];
__device__ __nv_bfloat16  g_o   [M_PAD * 256];
__device__ float          g_s2  [M_PAD * 256];
__device__ __nv_bfloat16  g_h   [M_PAD * 256];
__device__ __nv_bfloat16  g_g   [M_PAD * 1024];

__device__ __nv_bfloat16  g_wqkv[768 * 256];
__device__ __nv_bfloat16  g_wo  [256 * 256];
__device__ __nv_bfloat16  g_w1  [1024 * 256];
__device__ __nv_bfloat16  g_w2  [256 * 1024];

// ---------------- low-level helpers ----------------
__device__ __forceinline__ void cp16(void* s, const void* g) {
    unsigned sa = (unsigned)__cvta_generic_to_shared(s);
    asm volatile("cp.async.cg.shared.global [%0], [%1], 16;\n" :: "r"(sa), "l"(g));
}
__device__ __forceinline__ void cp_commit() { asm volatile("cp.async.commit_group;\n"); }
__device__ __forceinline__ void cp_wait1()  { asm volatile("cp.async.wait_group 1;\n"); }

__device__ __forceinline__ uint32_t smem_u32(const void* p) {
    return (uint32_t)__cvta_generic_to_shared(p);
}

// raw bf16 mma with ISA-defined fragment layout (m16n8k16, f32 accum)
__device__ __forceinline__ void mma16816(float* d,
                                         unsigned a0, unsigned a1, unsigned a2, unsigned a3,
                                         unsigned b0, unsigned b1) {
    asm volatile("mma.sync.aligned.m16n8k16.row.col.f32.bf16.bf16.f32 "
                 "{%0,%1,%2,%3}, {%4,%5,%6,%7}, {%8,%9}, {%0,%1,%2,%3};"
                 : "+f"(d[0]), "+f"(d[1]), "+f"(d[2]), "+f"(d[3])
                 : "r"(a0), "r"(a1), "r"(a2), "r"(a3), "r"(b0), "r"(b1));
}

__device__ __forceinline__ void ldsm_x4(unsigned& r0, unsigned& r1, unsigned& r2, unsigned& r3,
                                        uint32_t addr) {
    asm volatile("ldmatrix.sync.aligned.m8n8.x4.shared.b16 {%0,%1,%2,%3}, [%4];"
                 : "=r"(r0), "=r"(r1), "=r"(r2), "=r"(r3) : "r"(addr));
}

// ---------------- fused fp32 -> bf16 weight convert ----------------
__global__ void cvt_all_kernel(const float* __restrict__ a0, const float* __restrict__ a1,
                               const float* __restrict__ a2, const float* __restrict__ a3,
                               __nv_bfloat16* __restrict__ o0, __nv_bfloat16* __restrict__ o1,
                               __nv_bfloat16* __restrict__ o2, __nv_bfloat16* __restrict__ o3) {
    int i = blockIdx.x * 256 + threadIdx.x;
    if (i < 196608)       o0[i] = __float2bfloat16(a0[i]);
    else if (i < 262144)  o1[i - 196608] = __float2bfloat16(a1[i - 196608]);
    else if (i < 524288)  o2[i - 262144] = __float2bfloat16(a2[i - 262144]);
    else if (i < 786432)  o3[i - 524288] = __float2bfloat16(a3[i - 524288]);
}

// ---------------- fused NCHW->channels-last pad transpose + LN1 ----------------
__global__ void __launch_bounds__(256) lnin_kernel(
    const float* __restrict__ x, const float* __restrict__ pos,
    const float* __restrict__ gw, const float* __restrict__ gb,
    float* __restrict__ xpad, __nv_bfloat16* __restrict__ z)
{
    __shared__ float tile[256][33];
    const int tx = threadIdx.x, ty = threadIdx.y;
    const int h = blockIdx.y, b = blockIdx.z;
    const int w = blockIdx.x * 32 + tx;
    const bool hv = h < H_;
    const bool wv = w < W_;
#pragma unroll
    for (int j = 0; j < 32; j++) {
        int c = ty + 8 * j;
        float v = 0.f;
        if (hv && wv) v = x[(((size_t)b * 256 + c) * 200 + h) * 200 + w];
        tile[c][tx] = v;
    }
    __syncthreads();

    const int lane = tx;
    for (int tk = ty; tk < 32; tk += 8) {
        int wtok = blockIdx.x * 32 + tk;
        if (wtok >= WP_) break;
        size_t m = ((size_t)(b * HP_ + h)) * WP_ + wtok;
        int t = (h % WS_) * WS_ + (wtok % WS_);
        float v[8];
        float s = 0.f, sq = 0.f;
#pragma unroll
        for (int i = 0; i < 8; i++) {
            int c = lane + 32 * i;
            float xv = tile[c][tk];
            xpad[m * 256 + c] = xv;
            float vv = xv + pos[(size_t)t * 256 + c];
            v[i] = vv;
            s += vv; sq += vv * vv;
        }
#pragma unroll
        for (int o = 16; o; o >>= 1) {
            s  += __shfl_xor_sync(0xffffffffu, s,  o);
            sq += __shfl_xor_sync(0xffffffffu, sq, o);
        }
        float mean = s * (1.f / 256.f);
        float var  = sq * (1.f / 256.f) - mean * mean;
        float inv  = rsqrtf(var + 1e-5f);
#pragma unroll
        for (int i = 0; i < 8; i++) {
            int c = lane + 32 * i;
            z[m * 256 + c] = __float2bfloat16((v[i] - mean) * inv * gw[c] + gb[c]);
        }
    }
}

// ---------------- LayerNorm (LN2): one warp per token ----------------
__global__ void __launch_bounds__(256) ln_kernel(
    const float* __restrict__ in,
    const float* __restrict__ gw, const float* __restrict__ gb,
    __nv_bfloat16* __restrict__ out, int M)
{
    int m = blockIdx.x * 8 + (threadIdx.x >> 5);
    int lane = threadIdx.x & 31;
    if (m >= M) return;
    size_t base = (size_t)m * 256 + lane * 8;
    float4 a0 = *(const float4*)(in + base);
    float4 a1 = *(const float4*)(in + base + 4);
    float v[8] = {a0.x, a0.y, a0.z, a0.w, a1.x, a1.y, a1.z, a1.w};
    float s = 0.f, sq = 0.f;
#pragma unroll
    for (int i = 0; i < 8; i++) { s += v[i]; sq += v[i] * v[i]; }
#pragma unroll
    for (int o = 16; o; o >>= 1) {
        s  += __shfl_xor_sync(0xffffffffu, s,  o);
        sq += __shfl_xor_sync(0xffffffffu, sq, o);
    }
    float mean = s * (1.f / 256.f);
    float var  = sq * (1.f / 256.f) - mean * mean;
    float inv  = rsqrtf(var + 1e-5f);
    float4 w0 = *(const float4*)(gw + lane * 8);
    float4 w1 = *(const float4*)(gw + lane * 8 + 4);
    float4 b0 = *(const float4*)(gb + lane * 8);
    float4 b1 = *(const float4*)(gb + lane * 8 + 4);
    float wv[8] = {w0.x, w0.y, w0.z, w0.w, w1.x, w1.y, w1.z, w1.w};
    float bv[8] = {b0.x, b0.y, b0.z, b0.w, b1.x, b1.y, b1.z, b1.w};
    union { uint4 u; __nv_bfloat16 h[8]; } pk;
#pragma unroll
    for (int i = 0; i < 8; i++)
        pk.h[i] = __float2bfloat16((v[i] - mean) * inv * wv[i] + bv[i]);
    *(uint4*)(out + base) = pk.u;
}

// ---------------- raw-mma bf16 GEMM  C = A(MxK) * W(NxK)^T ----------------
// CTA tile 256x128, 512 threads (16 warps; warp tile 32x64), BK=64.
// smem per stage: A 256 rows x 128B (XOR-swizzled) + B 128 rows x 128B = 48KB;
// 3-stage cp.async ring (proven round-5 accounting). 147456 B total.
constexpr int GM_STAGE = 49152;
constexpr int GM_SMEM  = 3 * GM_STAGE;      // 147456 (EPI3 Cs 256x132 f32 = 135168 aliases)

template <int EPI>
__global__ void __launch_bounds__(512, 1) gemm_mma(
    const __nv_bfloat16* __restrict__ A, const __nv_bfloat16* __restrict__ Wt,
    const float* __restrict__ bias, int K, int NOUT,
    __nv_bfloat16* __restrict__ outb, float* __restrict__ outf,
    const float* __restrict__ resid, const float* __restrict__ pos)
{
    extern __shared__ char sm[];
    const uint32_t sb = smem_u32(sm);
    const int tid = threadIdx.x;
    const int wid = tid >> 5, lane = tid & 31;
    const int g = lane >> 2, c = lane & 3;
    const int wm = wid >> 1, wn = wid & 1;         // wm 0..7 (32 rows), wn 0..1 (64 cols)
    const int n0 = blockIdx.x * 128;
    const size_t m0 = (size_t)blockIdx.y * 256;

    const __nv_bfloat16* gA = A + m0 * K;
    const __nv_bfloat16* gB = Wt + (size_t)n0 * K;

    // fill stage st with K-chunk kt. A: 2048 16B-chunks, B: 1024. 6 cp16/thread.
    auto fill = [&](int kt, int st) {
        char* ab = sm + st * GM_STAGE;
#pragma unroll
        for (int it = 0; it < 4; it++) {          // A part
            int idx = tid + it * 512;
            int r = idx >> 3, c16 = idx & 7;
            cp16(ab + r * 128 + ((c16 ^ (r & 7)) << 4),
                 gA + (size_t)r * K + kt * 64 + c16 * 8);
        }
#pragma unroll
        for (int it = 0; it < 2; it++) {          // B part
            int idx = tid + it * 512;
            int r = idx >> 3, c16 = idx & 7;
            cp16(ab + 32768 + r * 128 + ((c16 ^ (r & 7)) << 4),
                 gB + (size_t)r * K + kt * 64 + c16 * 8);
        }
        cp_commit();
    };

    float acc[2][8][4];
#pragma unroll
    for (int mi = 0; mi < 2; mi++)
#pragma unroll
        for (int nt = 0; nt < 8; nt++)
#pragma unroll
            for (int j = 0; j < 4; j++) acc[mi][nt][j] = 0.f;

    const int KC = K / 64;
    fill(0, 0); fill(1, 1);

    // ldmatrix lane addressing constants for A frags
    const int a_row_in_tile = lane & 15;           // row within 16-row frag
    const int a_ch_half = lane >> 4;               // 0: cols 0-7, 1: cols 8-15

    for (int kt = 0; kt < KC; kt++) {
        cp_wait1();
        __syncthreads();
        if (kt + 2 < KC) fill(kt + 2, (kt + 2) % 3);
        else             cp_commit();              // keep group accounting exact
        const uint32_t ab = sb + (kt % 3) * GM_STAGE;
        const char*    bb = sm + (kt % 3) * GM_STAGE + 32768;
#pragma unroll
        for (int kk = 0; kk < 4; kk++) {
            unsigned afr[2][4];
#pragma unroll
            for (int mi = 0; mi < 2; mi++) {
                int row = wm * 32 + mi * 16 + a_row_in_tile;
                int ch  = kk * 2 + a_ch_half;
                ldsm_x4(afr[mi][0], afr[mi][1], afr[mi][2], afr[mi][3],
                        ab + row * 128 + (uint32_t)((ch ^ (row & 7)) << 4));
            }
#pragma unroll
            for (int nt = 0; nt < 8; nt++) {
                int n = wn * 64 + nt * 8 + g;
                const char* brow = bb + n * 128 + c * 4;
                unsigned b0 = *(const unsigned*)(brow + (((kk * 2)     ^ (n & 7)) << 4));
                unsigned b1 = *(const unsigned*)(brow + (((kk * 2 + 1) ^ (n & 7)) << 4));
                mma16816(acc[0][nt], afr[0][0], afr[0][1], afr[0][2], afr[0][3], b0, b1);
                mma16816(acc[1][nt], afr[1][0], afr[1][1], afr[1][2], afr[1][3], b0, b1);
            }
        }
    }

    // ---------- epilogues (register-direct except EPI3) ----------
    if (EPI == 0 || EPI == 2) {
        const float scale = (EPI == 0 && (n0 + wn * 64) < 256) ? 0.17677669529663689f : 1.f;
#pragma unroll
        for (int nt = 0; nt < 8; nt++) {
            int cb = n0 + wn * 64 + nt * 8 + 2 * c;
            float2 b2 = *(const float2*)(bias + cb);
#pragma unroll
            for (int mi = 0; mi < 2; mi++) {
                size_t r0 = m0 + wm * 32 + mi * 16 + g;
#pragma unroll
                for (int half = 0; half < 2; half++) {
                    size_t r = r0 + 8 * half;
                    float vx = acc[mi][nt][2 * half]     + b2.x;
                    float vy = acc[mi][nt][2 * half + 1] + b2.y;
                    if (EPI == 0) { vx *= scale; vy *= scale; }
                    else {
                        vx = 0.5f * vx * (1.f + erff(vx * 0.7071067811865475f));
                        vy = 0.5f * vy * (1.f + erff(vy * 0.7071067811865475f));
                    }
                    __nv_bfloat162 pk2 = __floats2bfloat162_rn(vx, vy);
                    *(unsigned*)(outb + r * NOUT + cb) = *(unsigned*)&pk2;
                }
            }
        }
    } else if (EPI == 1) {
#pragma unroll
        for (int mi = 0; mi < 2; mi++)
#pragma unroll
            for (int half = 0; half < 2; half++) {
                size_t m = m0 + wm * 32 + mi * 16 + g + 8 * half;
                int iw = (int)(m % WP_);
                int ih = (int)((m / WP_) % HP_);
                int t = (ih % WS_) * WS_ + (iw % WS_);
#pragma unroll
                for (int nt = 0; nt < 8; nt++) {
                    int cb = n0 + wn * 64 + nt * 8 + 2 * c;
                    float2 b2 = *(const float2*)(bias + cb);
                    float2 rs = *(const float2*)(resid + m * 256 + cb);
                    float2 pe = *(const float2*)(pos + (size_t)t * 256 + cb);
                    float2 ov;
                    ov.x = acc[mi][nt][2 * half]     + b2.x + rs.x + pe.x;
                    ov.y = acc[mi][nt][2 * half + 1] + b2.y + rs.y + pe.y;
                    *(float2*)(outf + m * 256 + cb) = ov;
                }
            }
    } else {
        // EPI 3: acc+bias -> Cs smem, += resid (coalesced), NCHW cropped store
        __syncthreads();
        float* Cs = (float*)sm;                    // 256 x 132
#pragma unroll
        for (int nt = 0; nt < 8; nt++) {
            int cl = wn * 64 + nt * 8 + 2 * c;
            float2 b2 = *(const float2*)(bias + n0 + cl);
#pragma unroll
            for (int mi = 0; mi < 2; mi++) {
                int r0 = wm * 32 + mi * 16 + g;
                Cs[(r0)     * 132 + cl]     = acc[mi][nt][0] + b2.x;
                Cs[(r0)     * 132 + cl + 1] = acc[mi][nt][1] + b2.y;
                Cs[(r0 + 8) * 132 + cl]     = acc[mi][nt][2] + b2.x;
                Cs[(r0 + 8) * 132 + cl + 1] = acc[mi][nt][3] + b2.y;
            }
        }
        __syncthreads();
        {
            int rr = tid >> 1, hf = tid & 1;
            const float* rsrow = resid + (m0 + rr) * 256 + n0 + hf * 64;
            float* csrow = Cs + rr * 132 + hf * 64;
#pragma unroll
            for (int j = 0; j < 16; j++) {
                float4 rv = *(const float4*)(rsrow + j * 4);
                float4 cv = *(const float4*)(csrow + j * 4);
                cv.x += rv.x; cv.y += rv.y; cv.z += rv.z; cv.w += rv.w;
                *(float4*)(csrow + j * 4) = cv;
            }
        }
        __syncthreads();
        {
            int tok = tid & 255, sel = tid >> 8;
            size_t m = m0 + tok;
            int iw = (int)(m % WP_);
            size_t q = m / WP_;
            int ih = (int)(q % HP_);
            int b = (int)(q / HP_);
            if (b < B_ && ih < H_ && iw < W_) {
                size_t base = (size_t)b * (256 * 200 * 200) + (size_t)ih * 200 + iw;
                for (int ci = sel; ci < 128; ci += 2)
                    outf[base + (size_t)(n0 + ci) * 40000] = Cs[tok * 132 + ci];
            }
        }
    }
}

// ---------------- windowed attention (register-softmax mma.sync, proven) ----------
constexpr int RPAD     = 40;
constexpr int HSTRIDE  = 49 * RPAD;
constexpr int ATTN_SMEM = (3 * 8 * HSTRIDE + 15 * RPAD) * 2;  // 95280 B -> 2 CTA/SM

__global__ void __launch_bounds__(256, 2) attn_kernel(
    const __nv_bfloat16* __restrict__ qkv, __nv_bfloat16* __restrict__ og)
{
    extern __shared__ char smem[];
    __nv_bfloat16* q_s = (__nv_bfloat16*)smem;
    __nv_bfloat16* k_s = q_s + 8 * HSTRIDE;
    __nv_bfloat16* v_s = k_s + 8 * HSTRIDE;

    const int win = blockIdx.x;
    const int b = win / (NWH * NWW);
    const int r = win % (NWH * NWW);
    const int wh = r / NWW, ww = r % NWW;
    const int tid = threadIdx.x;

    for (int i = tid; i < 49 * 96; i += 256) {
        int t = i / 96, ch = i % 96;
        int c0 = ch * 8;
        int ih = wh * WS_ + t / WS_, iw = ww * WS_ + t % WS_;
        size_t row = ((size_t)(b * HP_ + ih)) * WP_ + iw;
        uint4 val = *(const uint4*)(qkv + row * 768 + c0);
        int which = c0 >> 8;
        int cl = c0 & 255;
        int head = cl >> 5, d = cl & 31;
        __nv_bfloat16* base = (which == 0) ? q_s : (which == 1) ? k_s : v_s;
        *(uint4*)(base + head * HSTRIDE + t * RPAD + d) = val;
    }
    for (int i = tid; i < 75; i += 256)
        *(uint4*)(v_s + 8 * HSTRIDE + i * 8) = make_uint4(0, 0, 0, 0);
    __syncthreads();

    const int warp = tid >> 5, lane = tid & 31;
    const int g = lane >> 2, c = lane & 3;
    const __nv_bfloat16* qh = q_s + warp * HSTRIDE;
    const __nv_bfloat16* kh = k_s + warp * HSTRIDE;
    const __nv_bfloat16* vh = v_s + warp * HSTRIDE;

    unsigned kb[8][2][2];
#pragma unroll
    for (int nt = 0; nt < 8; nt++)
#pragma unroll
        for (int kc = 0; kc < 2; kc++) {
            const __nv_bfloat16* kr = kh + (8 * nt + g) * RPAD + 16 * kc + 2 * c;
            kb[nt][kc][0] = *(const unsigned*)kr;
            kb[nt][kc][1] = *(const unsigned*)(kr + 8);
        }

    for (int rt = 0; rt < 4; rt++) {
        unsigned qa[2][4];
#pragma unroll
        for (int kc = 0; kc < 2; kc++) {
            const __nv_bfloat16* q0 = qh + (16 * rt + g) * RPAD + 16 * kc + 2 * c;
            const __nv_bfloat16* q1 = q0 + 8 * RPAD;
            qa[kc][0] = *(const unsigned*)q0;
            qa[kc][1] = *(const unsigned*)q1;
            qa[kc][2] = *(const unsigned*)(q0 + 8);
            qa[kc][3] = *(const unsigned*)(q1 + 8);
        }

        float sa[8][4];
#pragma unroll
        for (int nt = 0; nt < 8; nt++) { sa[nt][0] = sa[nt][1] = sa[nt][2] = sa[nt][3] = 0.f; }
#pragma unroll
        for (int nt = 0; nt < 8; nt++)
#pragma unroll
            for (int kc = 0; kc < 2; kc++)
                mma16816(sa[nt], qa[kc][0], qa[kc][1], qa[kc][2], qa[kc][3],
                         kb[nt][kc][0], kb[nt][kc][1]);

#pragma unroll
        for (int nt = 6; nt < 8; nt++) {
            int col0 = 8 * nt + 2 * c;
            if (col0 >= 49)     { sa[nt][0] = -1e30f; sa[nt][2] = -1e30f; }
            if (col0 + 1 >= 49) { sa[nt][1] = -1e30f; sa[nt][3] = -1e30f; }
        }

        float mx0 = -1e30f, mx1 = -1e30f;
#pragma unroll
        for (int nt = 0; nt < 8; nt++) {
            mx0 = fmaxf(mx0, fmaxf(sa[nt][0], sa[nt][1]));
            mx1 = fmaxf(mx1, fmaxf(sa[nt][2], sa[nt][3]));
        }
        mx0 = fmaxf(mx0, __shfl_xor_sync(0xffffffffu, mx0, 1));
        mx0 = fmaxf(mx0, __shfl_xor_sync(0xffffffffu, mx0, 2));
        mx1 = fmaxf(mx1, __shfl_xor_sync(0xffffffffu, mx1, 1));
        mx1 = fmaxf(mx1, __shfl_xor_sync(0xffffffffu, mx1, 2));
        float sm0 = 0.f, sm1 = 0.f;
#pragma unroll
        for (int nt = 0; nt < 8; nt++) {
            sa[nt][0] = __expf(sa[nt][0] - mx0); sm0 += sa[nt][0];
            sa[nt][1] = __expf(sa[nt][1] - mx0); sm0 += sa[nt][1];
            sa[nt][2] = __expf(sa[nt][2] - mx1); sm1 += sa[nt][2];
            sa[nt][3] = __expf(sa[nt][3] - mx1); sm1 += sa[nt][3];
        }
        sm0 += __shfl_xor_sync(0xffffffffu, sm0, 1);
        sm0 += __shfl_xor_sync(0xffffffffu, sm0, 2);
        sm1 += __shfl_xor_sync(0xffffffffu, sm1, 1);
        sm1 += __shfl_xor_sync(0xffffffffu, sm1, 2);
        float inv0 = 1.f / sm0, inv1 = 1.f / sm1;

        unsigned pa[4][4];
#pragma unroll
        for (int kc = 0; kc < 4; kc++) {
            __nv_bfloat162 t0 = __floats2bfloat162_rn(sa[2 * kc][0] * inv0, sa[2 * kc][1] * inv0);
            __nv_bfloat162 t1 = __floats2bfloat162_rn(sa[2 * kc][2] * inv1, sa[2 * kc][3] * inv1);
            __nv_bfloat162 t2 = __floats2bfloat162_rn(sa[2 * kc + 1][0] * inv0, sa[2 * kc + 1][1] * inv0);
            __nv_bfloat162 t3 = __floats2bfloat162_rn(sa[2 * kc + 1][2] * inv1, sa[2 * kc + 1][3] * inv1);
            pa[kc][0] = *(unsigned*)&t0; pa[kc][1] = *(unsigned*)&t1;
            pa[kc][2] = *(unsigned*)&t2; pa[kc][3] = *(unsigned*)&t3;
        }

        float oa[4][4];
#pragma unroll
        for (int nt = 0; nt < 4; nt++) { oa[nt][0] = oa[nt][1] = oa[nt][2] = oa[nt][3] = 0.f; }
#pragma unroll
        for (int kc = 0; kc < 4; kc++)
#pragma unroll
            for (int nt = 0; nt < 4; nt++) {
                const unsigned short* vp =
                    (const unsigned short*)(vh + (16 * kc + 2 * c) * RPAD + 8 * nt + g);
                unsigned b0 = (unsigned)vp[0] | ((unsigned)vp[RPAD] << 16);
                unsigned b1 = (unsigned)vp[8 * RPAD] | ((unsigned)vp[9 * RPAD] << 16);
                mma16816(oa[nt], pa[kc][0], pa[kc][1], pa[kc][2], pa[kc][3], b0, b1);
            }

        int t0r = 16 * rt + g, t1r = t0r + 8;
#pragma unroll
        for (int half = 0; half < 2; half++) {
            int t = half ? t1r : t0r;
            if (t < 49) {
                int ih = wh * WS_ + t / WS_, iw = ww * WS_ + t % WS_;
                size_t row = ((size_t)(b * HP_ + ih)) * WP_ + iw;
                __nv_bfloat16* orow = og + row * 256 + warp * 32 + 2 * c;
#pragma unroll
                for (int nt = 0; nt < 4; nt++) {
                    __nv_bfloat162 pk2 = half
                        ? __floats2bfloat162_rn(oa[nt][2], oa[nt][3])
                        : __floats2bfloat162_rn(oa[nt][0], oa[nt][1]);
                    *(unsigned*)(orow + 8 * nt) = *(unsigned*)&pk2;
                }
            }
        }
    }
}

// ---------------- launch ----------------
extern "C" void kernel_launch(void* const* d_in, const int* in_sizes, int n_in,
                              void* d_out, int out_size)
{
    const float* x          = (const float*)d_in[0];
    const float* pos        = (const float*)d_in[1];
    const float* in_proj_w  = (const float*)d_in[2];
    const float* in_proj_b  = (const float*)d_in[3];
    const float* out_proj_w = (const float*)d_in[4];
    const float* out_proj_b = (const float*)d_in[5];
    const float* ln1_w      = (const float*)d_in[6];
    const float* ln1_b      = (const float*)d_in[7];
    const float* ln2_w      = (const float*)d_in[8];
    const float* ln2_b      = (const float*)d_in[9];
    const float* ff1_w      = (const float*)d_in[10];
    const float* ff1_b      = (const float*)d_in[11];
    const float* ff2_w      = (const float*)d_in[12];
    const float* ff2_b      = (const float*)d_in[13];
    float* out = (float*)d_out;

    void *p_xpad, *p_z, *p_qkv, *p_o, *p_s2, *p_h, *p_g;
    void *p_wqkv, *p_wo, *p_w1, *p_w2;
    cudaGetSymbolAddress(&p_xpad, g_xpad);
    cudaGetSymbolAddress(&p_z,    g_z);
    cudaGetSymbolAddress(&p_qkv,  g_qkv);
    cudaGetSymbolAddress(&p_o,    g_o);
    cudaGetSymbolAddress(&p_s2,   g_s2);
    cudaGetSymbolAddress(&p_h,    g_h);
    cudaGetSymbolAddress(&p_g,    g_g);
    cudaGetSymbolAddress(&p_wqkv, g_wqkv);
    cudaGetSymbolAddress(&p_wo,   g_wo);
    cudaGetSymbolAddress(&p_w1,   g_w1);
    cudaGetSymbolAddress(&p_w2,   g_w2);

    float* xpad = (float*)p_xpad;
    __nv_bfloat16* z    = (__nv_bfloat16*)p_z;
    __nv_bfloat16* qkv  = (__nv_bfloat16*)p_qkv;
    __nv_bfloat16* o_   = (__nv_bfloat16*)p_o;
    float* s2 = (float*)p_s2;
    __nv_bfloat16* h_   = (__nv_bfloat16*)p_h;
    __nv_bfloat16* gbuf = (__nv_bfloat16*)p_g;
    __nv_bfloat16* wqkv = (__nv_bfloat16*)p_wqkv;
    __nv_bfloat16* wo   = (__nv_bfloat16*)p_wo;
    __nv_bfloat16* w1   = (__nv_bfloat16*)p_w1;
    __nv_bfloat16* w2   = (__nv_bfloat16*)p_w2;

    cudaFuncSetAttribute(gemm_mma<0>, cudaFuncAttributeMaxDynamicSharedMemorySize, GM_SMEM);
    cudaFuncSetAttribute(gemm_mma<1>, cudaFuncAttributeMaxDynamicSharedMemorySize, GM_SMEM);
    cudaFuncSetAttribute(gemm_mma<2>, cudaFuncAttributeMaxDynamicSharedMemorySize, GM_SMEM);
    cudaFuncSetAttribute(gemm_mma<3>, cudaFuncAttributeMaxDynamicSharedMemorySize, GM_SMEM);
    cudaFuncSetAttribute(attn_kernel, cudaFuncAttributeMaxDynamicSharedMemorySize, ATTN_SMEM);

    // weights -> bf16
    cvt_all_kernel<<<3072, 256>>>(in_proj_w, out_proj_w, ff1_w, ff2_w, wqkv, wo, w1, w2);

    // fused pad-transpose + LN1
    lnin_kernel<<<dim3(7, HP_, B_), dim3(32, 8)>>>(x, pos, ln1_w, ln1_b, xpad, z);

    // QKV GEMM
    gemm_mma<0><<<dim3(6, MT256), 512, GM_SMEM>>>(z, wqkv, in_proj_b, 256, 768,
                                                  qkv, nullptr, nullptr, nullptr);
    // attention
    attn_kernel<<<NWIN, 256, ATTN_SMEM>>>(qkv, o_);

    // out proj + residual(x+pos) -> s2
    gemm_mma<1><<<dim3(2, MT256), 512, GM_SMEM>>>(o_, wo, out_proj_b, 256, 256,
                                                  nullptr, s2, xpad, pos);
    // LN2
    ln_kernel<<<((int)M_TOT + 7) / 8, 256>>>(s2, ln2_w, ln2_b, h_, (int)M_TOT);

    // FF1 + gelu
    gemm_mma<2><<<dim3(8, MT256), 512, GM_SMEM>>>(h_, w1, ff1_b, 256, 1024,
                                                  gbuf, nullptr, nullptr, nullptr);
    // FF2 + residual -> direct NCHW cropped output
    gemm_mma<3><<<dim3(2, MT256), 512, GM_SMEM>>>(gbuf, w2, ff2_b, 1024, 256,
                                                  nullptr, out, s2, nullptr);
}

// round 9
// speedup vs baseline: 2.2215x; 1.0236x over previous
#include <cuda_runtime.h>
#include <cuda_bf16.h>
#include <cstdint>
#include <math.h>

// ---------------- problem constants ----------------
constexpr int  B_   = 8;
constexpr int  C_   = 256;
constexpr int  H_   = 200;
constexpr int  W_   = 200;
constexpr int  WS_  = 7;
constexpr int  HP_  = 203;
constexpr int  WP_  = 203;
constexpr int  NWH  = 29;
constexpr int  NWW  = 29;
constexpr int  NWIN = B_ * NWH * NWW;              // 6728
constexpr size_t M_TOT = (size_t)B_ * HP_ * WP_;   // 329672 real tokens
constexpr int  MT256  = 1288;                      // M_PAD / 256
constexpr size_t M_PAD = (size_t)MT256 * 256;      // 329728 (GEMMs run guard-free)

// ---------------- scratch (device globals; zero-initialized) ----------------
__device__ float          g_xpad[M_PAD * 256];
__device__ __nv_bfloat16  g_z   [M_PAD * 256];
__device__ __nv_bfloat16  g_qkv [M_PAD * 768];
__device__ __nv_bfloat16  g_o   [M_PAD * 256];
__device__ float          g_s2  [M_PAD * 256];
__device__ __nv_bfloat16  g_h   [M_PAD * 256];
__device__ __nv_bfloat16  g_g   [M_PAD * 1024];

__device__ __nv_bfloat16  g_wqkv[768 * 256];
__device__ __nv_bfloat16  g_wo  [256 * 256];
__device__ __nv_bfloat16  g_w1  [1024 * 256];
__device__ __nv_bfloat16  g_w2  [256 * 1024];

// ---------------- low-level helpers ----------------
__device__ __forceinline__ void cp16(void* s, const void* g) {
    unsigned sa = (unsigned)__cvta_generic_to_shared(s);
    asm volatile("cp.async.cg.shared.global [%0], [%1], 16;\n" :: "r"(sa), "l"(g));
}
__device__ __forceinline__ void cp_commit() { asm volatile("cp.async.commit_group;\n"); }
__device__ __forceinline__ void cp_wait1()  { asm volatile("cp.async.wait_group 1;\n"); }

__device__ __forceinline__ uint32_t smem_u32(const void* p) {
    return (uint32_t)__cvta_generic_to_shared(p);
}

// raw bf16 mma with ISA-defined fragment layout (m16n8k16, f32 accum)
__device__ __forceinline__ void mma16816(float* d,
                                         unsigned a0, unsigned a1, unsigned a2, unsigned a3,
                                         unsigned b0, unsigned b1) {
    asm volatile("mma.sync.aligned.m16n8k16.row.col.f32.bf16.bf16.f32 "
                 "{%0,%1,%2,%3}, {%4,%5,%6,%7}, {%8,%9}, {%0,%1,%2,%3};"
                 : "+f"(d[0]), "+f"(d[1]), "+f"(d[2]), "+f"(d[3])
                 : "r"(a0), "r"(a1), "r"(a2), "r"(a3), "r"(b0), "r"(b1));
}

__device__ __forceinline__ void ldsm_x4(unsigned& r0, unsigned& r1, unsigned& r2, unsigned& r3,
                                        uint32_t addr) {
    asm volatile("ldmatrix.sync.aligned.m8n8.x4.shared.b16 {%0,%1,%2,%3}, [%4];"
                 : "=r"(r0), "=r"(r1), "=r"(r2), "=r"(r3) : "r"(addr));
}

// ---------------- fused fp32 -> bf16 weight convert ----------------
__global__ void cvt_all_kernel(const float* __restrict__ a0, const float* __restrict__ a1,
                               const float* __restrict__ a2, const float* __restrict__ a3,
                               __nv_bfloat16* __restrict__ o0, __nv_bfloat16* __restrict__ o1,
                               __nv_bfloat16* __restrict__ o2, __nv_bfloat16* __restrict__ o3) {
    int i = blockIdx.x * 256 + threadIdx.x;
    if (i < 196608)       o0[i] = __float2bfloat16(a0[i]);
    else if (i < 262144)  o1[i - 196608] = __float2bfloat16(a1[i - 196608]);
    else if (i < 524288)  o2[i - 262144] = __float2bfloat16(a2[i - 262144]);
    else if (i < 786432)  o3[i - 524288] = __float2bfloat16(a3[i - 524288]);
}

// ---------------- fused NCHW->channels-last pad transpose + LN1 ----------------
__global__ void __launch_bounds__(256) lnin_kernel(
    const float* __restrict__ x, const float* __restrict__ pos,
    const float* __restrict__ gw, const float* __restrict__ gb,
    float* __restrict__ xpad, __nv_bfloat16* __restrict__ z)
{
    __shared__ float tile[256][33];
    const int tx = threadIdx.x, ty = threadIdx.y;
    const int h = blockIdx.y, b = blockIdx.z;
    const int w = blockIdx.x * 32 + tx;
    const bool hv = h < H_;
    const bool wv = w < W_;
#pragma unroll
    for (int j = 0; j < 32; j++) {
        int c = ty + 8 * j;
        float v = 0.f;
        if (hv && wv) v = x[(((size_t)b * 256 + c) * 200 + h) * 200 + w];
        tile[c][tx] = v;
    }
    __syncthreads();

    const int lane = tx;
    for (int tk = ty; tk < 32; tk += 8) {
        int wtok = blockIdx.x * 32 + tk;
        if (wtok >= WP_) break;
        size_t m = ((size_t)(b * HP_ + h)) * WP_ + wtok;
        int t = (h % WS_) * WS_ + (wtok % WS_);
        float v[8];
        float s = 0.f, sq = 0.f;
#pragma unroll
        for (int i = 0; i < 8; i++) {
            int c = lane + 32 * i;
            float xv = tile[c][tk];
            xpad[m * 256 + c] = xv;
            float vv = xv + pos[(size_t)t * 256 + c];
            v[i] = vv;
            s += vv; sq += vv * vv;
        }
#pragma unroll
        for (int o = 16; o; o >>= 1) {
            s  += __shfl_xor_sync(0xffffffffu, s,  o);
            sq += __shfl_xor_sync(0xffffffffu, sq, o);
        }
        float mean = s * (1.f / 256.f);
        float var  = sq * (1.f / 256.f) - mean * mean;
        float inv  = rsqrtf(var + 1e-5f);
#pragma unroll
        for (int i = 0; i < 8; i++) {
            int c = lane + 32 * i;
            z[m * 256 + c] = __float2bfloat16((v[i] - mean) * inv * gw[c] + gb[c]);
        }
    }
}

// ---------------- LayerNorm (LN2): one warp per token ----------------
__global__ void __launch_bounds__(256) ln_kernel(
    const float* __restrict__ in,
    const float* __restrict__ gw, const float* __restrict__ gb,
    __nv_bfloat16* __restrict__ out, int M)
{
    int m = blockIdx.x * 8 + (threadIdx.x >> 5);
    int lane = threadIdx.x & 31;
    if (m >= M) return;
    size_t base = (size_t)m * 256 + lane * 8;
    float4 a0 = *(const float4*)(in + base);
    float4 a1 = *(const float4*)(in + base + 4);
    float v[8] = {a0.x, a0.y, a0.z, a0.w, a1.x, a1.y, a1.z, a1.w};
    float s = 0.f, sq = 0.f;
#pragma unroll
    for (int i = 0; i < 8; i++) { s += v[i]; sq += v[i] * v[i]; }
#pragma unroll
    for (int o = 16; o; o >>= 1) {
        s  += __shfl_xor_sync(0xffffffffu, s,  o);
        sq += __shfl_xor_sync(0xffffffffu, sq, o);
    }
    float mean = s * (1.f / 256.f);
    float var  = sq * (1.f / 256.f) - mean * mean;
    float inv  = rsqrtf(var + 1e-5f);
    float4 w0 = *(const float4*)(gw + lane * 8);
    float4 w1 = *(const float4*)(gw + lane * 8 + 4);
    float4 b0 = *(const float4*)(gb + lane * 8);
    float4 b1 = *(const float4*)(gb + lane * 8 + 4);
    float wv[8] = {w0.x, w0.y, w0.z, w0.w, w1.x, w1.y, w1.z, w1.w};
    float bv[8] = {b0.x, b0.y, b0.z, b0.w, b1.x, b1.y, b1.z, b1.w};
    union { uint4 u; __nv_bfloat16 h[8]; } pk;
#pragma unroll
    for (int i = 0; i < 8; i++)
        pk.h[i] = __float2bfloat16((v[i] - mean) * inv * wv[i] + bv[i]);
    *(uint4*)(out + base) = pk.u;
}

// ---------------- raw-mma bf16 GEMM  C = A(MxK) * W(NxK)^T ----------------
// CTA tile 256x128, 256 threads (8 warps; warp tile 64x64), BK=64.
// A and B fragments both via ldmatrix.x4 from XOR-swizzled 128B rows.
// 3-stage cp.async ring (proven accounting). 147456 B smem total.
constexpr int GM_STAGE = 49152;
constexpr int GM_SMEM  = 3 * GM_STAGE;      // 147456 (EPI3 Cs 256x132 f32 = 135168 aliases)

template <int EPI>
__global__ void __launch_bounds__(256, 1) gemm_mma(
    const __nv_bfloat16* __restrict__ A, const __nv_bfloat16* __restrict__ Wt,
    const float* __restrict__ bias, int K, int NOUT,
    __nv_bfloat16* __restrict__ outb, float* __restrict__ outf,
    const float* __restrict__ resid, const float* __restrict__ pos)
{
    extern __shared__ char sm[];
    const uint32_t sb = smem_u32(sm);
    const int tid = threadIdx.x;
    const int wid = tid >> 5, lane = tid & 31;
    const int g = lane >> 2, c = lane & 3;
    const int wm = wid >> 1, wn = wid & 1;         // wm 0..3 (64 rows), wn 0..1 (64 cols)
    const int n0 = blockIdx.x * 128;
    const size_t m0 = (size_t)blockIdx.y * 256;

    const __nv_bfloat16* gA = A + m0 * K;
    const __nv_bfloat16* gB = Wt + (size_t)n0 * K;

    // fill stage st with K-chunk kt. A: 2048 16B-chunks, B: 1024. 12 cp16/thread.
    auto fill = [&](int kt, int st) {
        char* ab = sm + st * GM_STAGE;
#pragma unroll
        for (int it = 0; it < 8; it++) {          // A part
            int idx = tid + it * 256;
            int r = idx >> 3, c16 = idx & 7;
            cp16(ab + r * 128 + ((c16 ^ (r & 7)) << 4),
                 gA + (size_t)r * K + kt * 64 + c16 * 8);
        }
#pragma unroll
        for (int it = 0; it < 4; it++) {          // B part
            int idx = tid + it * 256;
            int r = idx >> 3, c16 = idx & 7;
            cp16(ab + 32768 + r * 128 + ((c16 ^ (r & 7)) << 4),
                 gB + (size_t)r * K + kt * 64 + c16 * 8);
        }
        cp_commit();
    };

    float acc[4][8][4];
#pragma unroll
    for (int mi = 0; mi < 4; mi++)
#pragma unroll
        for (int nt = 0; nt < 8; nt++)
#pragma unroll
            for (int j = 0; j < 4; j++) acc[mi][nt][j] = 0.f;

    const int KC = K / 64;
    fill(0, 0); fill(1, 1);

    // lane addressing precomputed pieces
    const int a_row_lo = lane & 15;                // row within 16-row A frag
    const int a_ch_half = lane >> 4;               // 0: k 0-7, 1: k 8-15
    const int b_tile = lane >> 3;                  // 0..3
    const int b_row  = lane & 7;                   // row within 8-row B tile

    for (int kt = 0; kt < KC; kt++) {
        cp_wait1();
        __syncthreads();
        if (kt + 2 < KC) fill(kt + 2, (kt + 2) % 3);
        else             cp_commit();              // keep group accounting exact
        const uint32_t ab  = sb + (kt % 3) * GM_STAGE;
        const uint32_t bbm = ab + 32768;
#pragma unroll
        for (int kk = 0; kk < 4; kk++) {
            unsigned afr[4][4];
#pragma unroll
            for (int mi = 0; mi < 4; mi++) {
                int row = wm * 64 + mi * 16 + a_row_lo;
                int ch  = kk * 2 + a_ch_half;
                ldsm_x4(afr[mi][0], afr[mi][1], afr[mi][2], afr[mi][3],
                        ab + row * 128 + (uint32_t)((ch ^ (row & 7)) << 4));
            }
#pragma unroll
            for (int np = 0; np < 4; np++) {
                // B tiles: t=0 -> (nt=2np, k-lo), t=1 -> (nt=2np, k-hi),
                //          t=2 -> (nt=2np+1, k-lo), t=3 -> (nt=2np+1, k-hi)
                int n = wn * 64 + np * 16 + ((b_tile >> 1) << 3) + b_row;
                int chunk = kk * 2 + (b_tile & 1);
                unsigned bfr0, bfr1, bfr2, bfr3;
                ldsm_x4(bfr0, bfr1, bfr2, bfr3,
                        bbm + n * 128 + (uint32_t)((chunk ^ b_row) << 4));
#pragma unroll
                for (int mi = 0; mi < 4; mi++) {
                    mma16816(acc[mi][2 * np],     afr[mi][0], afr[mi][1], afr[mi][2], afr[mi][3], bfr0, bfr1);
                    mma16816(acc[mi][2 * np + 1], afr[mi][0], afr[mi][1], afr[mi][2], afr[mi][3], bfr2, bfr3);
                }
            }
        }
    }

    // ---------- epilogues (register-direct except EPI3) ----------
    if (EPI == 0 || EPI == 2) {
        const float scale = (EPI == 0 && n0 < 256) ? 0.17677669529663689f : 1.f;
#pragma unroll
        for (int nt = 0; nt < 8; nt++) {
            int cb = n0 + wn * 64 + nt * 8 + 2 * c;
            float2 b2 = *(const float2*)(bias + cb);
#pragma unroll
            for (int mi = 0; mi < 4; mi++) {
                size_t r0 = m0 + wm * 64 + mi * 16 + g;
#pragma unroll
                for (int half = 0; half < 2; half++) {
                    size_t r = r0 + 8 * half;
                    float vx = acc[mi][nt][2 * half]     + b2.x;
                    float vy = acc[mi][nt][2 * half + 1] + b2.y;
                    if (EPI == 0) { vx *= scale; vy *= scale; }
                    else {
                        vx = 0.5f * vx * (1.f + erff(vx * 0.7071067811865475f));
                        vy = 0.5f * vy * (1.f + erff(vy * 0.7071067811865475f));
                    }
                    __nv_bfloat162 pk2 = __floats2bfloat162_rn(vx, vy);
                    *(unsigned*)(outb + r * NOUT + cb) = *(unsigned*)&pk2;
                }
            }
        }
    } else if (EPI == 1) {
#pragma unroll
        for (int mi = 0; mi < 4; mi++)
#pragma unroll
            for (int half = 0; half < 2; half++) {
                size_t m = m0 + wm * 64 + mi * 16 + g + 8 * half;
                int iw = (int)(m % WP_);
                int ih = (int)((m / WP_) % HP_);
                int t = (ih % WS_) * WS_ + (iw % WS_);
#pragma unroll
                for (int nt = 0; nt < 8; nt++) {
                    int cb = n0 + wn * 64 + nt * 8 + 2 * c;
                    float2 b2 = *(const float2*)(bias + cb);
                    float2 rs = *(const float2*)(resid + m * 256 + cb);
                    float2 pe = *(const float2*)(pos + (size_t)t * 256 + cb);
                    float2 ov;
                    ov.x = acc[mi][nt][2 * half]     + b2.x + rs.x + pe.x;
                    ov.y = acc[mi][nt][2 * half + 1] + b2.y + rs.y + pe.y;
                    *(float2*)(outf + m * 256 + cb) = ov;
                }
            }
    } else {
        // EPI 3: acc+bias -> Cs smem, += resid (coalesced), NCHW cropped store
        __syncthreads();
        float* Cs = (float*)sm;                    // 256 x 132
#pragma unroll
        for (int nt = 0; nt < 8; nt++) {
            int cl = wn * 64 + nt * 8 + 2 * c;
            float2 b2 = *(const float2*)(bias + n0 + cl);
#pragma unroll
            for (int mi = 0; mi < 4; mi++) {
                int r0 = wm * 64 + mi * 16 + g;
                Cs[(r0)     * 132 + cl]     = acc[mi][nt][0] + b2.x;
                Cs[(r0)     * 132 + cl + 1] = acc[mi][nt][1] + b2.y;
                Cs[(r0 + 8) * 132 + cl]     = acc[mi][nt][2] + b2.x;
                Cs[(r0 + 8) * 132 + cl + 1] = acc[mi][nt][3] + b2.y;
            }
        }
        __syncthreads();
        {
            int rr = tid;                          // one row per thread
            const float* rsrow = resid + (m0 + rr) * 256 + n0;
            float* csrow = Cs + rr * 132;
#pragma unroll
            for (int j = 0; j < 32; j++) {
                float4 rv = *(const float4*)(rsrow + j * 4);
                float4 cv = *(const float4*)(csrow + j * 4);
                cv.x += rv.x; cv.y += rv.y; cv.z += rv.z; cv.w += rv.w;
                *(float4*)(csrow + j * 4) = cv;
            }
        }
        __syncthreads();
        {
            int tok = tid;
            size_t m = m0 + tok;
            int iw = (int)(m % WP_);
            size_t q = m / WP_;
            int ih = (int)(q % HP_);
            int b = (int)(q / HP_);
            if (b < B_ && ih < H_ && iw < W_) {
                size_t base = (size_t)b * (256 * 200 * 200) + (size_t)ih * 200 + iw;
                for (int ci = 0; ci < 128; ci++)
                    outf[base + (size_t)(n0 + ci) * 40000] = Cs[tok * 132 + ci];
            }
        }
    }
}

// ---------------- windowed attention (register-softmax mma.sync, proven) ----------
constexpr int RPAD     = 40;
constexpr int HSTRIDE  = 49 * RPAD;
constexpr int ATTN_SMEM = (3 * 8 * HSTRIDE + 15 * RPAD) * 2;  // 95280 B -> 2 CTA/SM

__global__ void __launch_bounds__(256, 2) attn_kernel(
    const __nv_bfloat16* __restrict__ qkv, __nv_bfloat16* __restrict__ og)
{
    extern __shared__ char smem[];
    __nv_bfloat16* q_s = (__nv_bfloat16*)smem;
    __nv_bfloat16* k_s = q_s + 8 * HSTRIDE;
    __nv_bfloat16* v_s = k_s + 8 * HSTRIDE;

    const int win = blockIdx.x;
    const int b = win / (NWH * NWW);
    const int r = win % (NWH * NWW);
    const int wh = r / NWW, ww = r % NWW;
    const int tid = threadIdx.x;

    for (int i = tid; i < 49 * 96; i += 256) {
        int t = i / 96, ch = i % 96;
        int c0 = ch * 8;
        int ih = wh * WS_ + t / WS_, iw = ww * WS_ + t % WS_;
        size_t row = ((size_t)(b * HP_ + ih)) * WP_ + iw;
        uint4 val = *(const uint4*)(qkv + row * 768 + c0);
        int which = c0 >> 8;
        int cl = c0 & 255;
        int head = cl >> 5, d = cl & 31;
        __nv_bfloat16* base = (which == 0) ? q_s : (which == 1) ? k_s : v_s;
        *(uint4*)(base + head * HSTRIDE + t * RPAD + d) = val;
    }
    for (int i = tid; i < 75; i += 256)
        *(uint4*)(v_s + 8 * HSTRIDE + i * 8) = make_uint4(0, 0, 0, 0);
    __syncthreads();

    const int warp = tid >> 5, lane = tid & 31;
    const int g = lane >> 2, c = lane & 3;
    const __nv_bfloat16* qh = q_s + warp * HSTRIDE;
    const __nv_bfloat16* kh = k_s + warp * HSTRIDE;
    const __nv_bfloat16* vh = v_s + warp * HSTRIDE;

    unsigned kb[8][2][2];
#pragma unroll
    for (int nt = 0; nt < 8; nt++)
#pragma unroll
        for (int kc = 0; kc < 2; kc++) {
            const __nv_bfloat16* kr = kh + (8 * nt + g) * RPAD + 16 * kc + 2 * c;
            kb[nt][kc][0] = *(const unsigned*)kr;
            kb[nt][kc][1] = *(const unsigned*)(kr + 8);
        }

    for (int rt = 0; rt < 4; rt++) {
        unsigned qa[2][4];
#pragma unroll
        for (int kc = 0; kc < 2; kc++) {
            const __nv_bfloat16* q0 = qh + (16 * rt + g) * RPAD + 16 * kc + 2 * c;
            const __nv_bfloat16* q1 = q0 + 8 * RPAD;
            qa[kc][0] = *(const unsigned*)q0;
            qa[kc][1] = *(const unsigned*)q1;
            qa[kc][2] = *(const unsigned*)(q0 + 8);
            qa[kc][3] = *(const unsigned*)(q1 + 8);
        }

        float sa[8][4];
#pragma unroll
        for (int nt = 0; nt < 8; nt++) { sa[nt][0] = sa[nt][1] = sa[nt][2] = sa[nt][3] = 0.f; }
#pragma unroll
        for (int nt = 0; nt < 8; nt++)
#pragma unroll
            for (int kc = 0; kc < 2; kc++)
                mma16816(sa[nt], qa[kc][0], qa[kc][1], qa[kc][2], qa[kc][3],
                         kb[nt][kc][0], kb[nt][kc][1]);

#pragma unroll
        for (int nt = 6; nt < 8; nt++) {
            int col0 = 8 * nt + 2 * c;
            if (col0 >= 49)     { sa[nt][0] = -1e30f; sa[nt][2] = -1e30f; }
            if (col0 + 1 >= 49) { sa[nt][1] = -1e30f; sa[nt][3] = -1e30f; }
        }

        float mx0 = -1e30f, mx1 = -1e30f;
#pragma unroll
        for (int nt = 0; nt < 8; nt++) {
            mx0 = fmaxf(mx0, fmaxf(sa[nt][0], sa[nt][1]));
            mx1 = fmaxf(mx1, fmaxf(sa[nt][2], sa[nt][3]));
        }
        mx0 = fmaxf(mx0, __shfl_xor_sync(0xffffffffu, mx0, 1));
        mx0 = fmaxf(mx0, __shfl_xor_sync(0xffffffffu, mx0, 2));
        mx1 = fmaxf(mx1, __shfl_xor_sync(0xffffffffu, mx1, 1));
        mx1 = fmaxf(mx1, __shfl_xor_sync(0xffffffffu, mx1, 2));
        float sm0 = 0.f, sm1 = 0.f;
#pragma unroll
        for (int nt = 0; nt < 8; nt++) {
            sa[nt][0] = __expf(sa[nt][0] - mx0); sm0 += sa[nt][0];
            sa[nt][1] = __expf(sa[nt][1] - mx0); sm0 += sa[nt][1];
            sa[nt][2] = __expf(sa[nt][2] - mx1); sm1 += sa[nt][2];
            sa[nt][3] = __expf(sa[nt][3] - mx1); sm1 += sa[nt][3];
        }
        sm0 += __shfl_xor_sync(0xffffffffu, sm0, 1);
        sm0 += __shfl_xor_sync(0xffffffffu, sm0, 2);
        sm1 += __shfl_xor_sync(0xffffffffu, sm1, 1);
        sm1 += __shfl_xor_sync(0xffffffffu, sm1, 2);
        float inv0 = 1.f / sm0, inv1 = 1.f / sm1;

        unsigned pa[4][4];
#pragma unroll
        for (int kc = 0; kc < 4; kc++) {
            __nv_bfloat162 t0 = __floats2bfloat162_rn(sa[2 * kc][0] * inv0, sa[2 * kc][1] * inv0);
            __nv_bfloat162 t1 = __floats2bfloat162_rn(sa[2 * kc][2] * inv1, sa[2 * kc][3] * inv1);
            __nv_bfloat162 t2 = __floats2bfloat162_rn(sa[2 * kc + 1][0] * inv0, sa[2 * kc + 1][1] * inv0);
            __nv_bfloat162 t3 = __floats2bfloat162_rn(sa[2 * kc + 1][2] * inv1, sa[2 * kc + 1][3] * inv1);
            pa[kc][0] = *(unsigned*)&t0; pa[kc][1] = *(unsigned*)&t1;
            pa[kc][2] = *(unsigned*)&t2; pa[kc][3] = *(unsigned*)&t3;
        }

        float oa[4][4];
#pragma unroll
        for (int nt = 0; nt < 4; nt++) { oa[nt][0] = oa[nt][1] = oa[nt][2] = oa[nt][3] = 0.f; }
#pragma unroll
        for (int kc = 0; kc < 4; kc++)
#pragma unroll
            for (int nt = 0; nt < 4; nt++) {
                const unsigned short* vp =
                    (const unsigned short*)(vh + (16 * kc + 2 * c) * RPAD + 8 * nt + g);
                unsigned b0 = (unsigned)vp[0] | ((unsigned)vp[RPAD] << 16);
                unsigned b1 = (unsigned)vp[8 * RPAD] | ((unsigned)vp[9 * RPAD] << 16);
                mma16816(oa[nt], pa[kc][0], pa[kc][1], pa[kc][2], pa[kc][3], b0, b1);
            }

        int t0r = 16 * rt + g, t1r = t0r + 8;
#pragma unroll
        for (int half = 0; half < 2; half++) {
            int t = half ? t1r : t0r;
            if (t < 49) {
                int ih = wh * WS_ + t / WS_, iw = ww * WS_ + t % WS_;
                size_t row = ((size_t)(b * HP_ + ih)) * WP_ + iw;
                __nv_bfloat16* orow = og + row * 256 + warp * 32 + 2 * c;
#pragma unroll
                for (int nt = 0; nt < 4; nt++) {
                    __nv_bfloat162 pk2 = half
                        ? __floats2bfloat162_rn(oa[nt][2], oa[nt][3])
                        : __floats2bfloat162_rn(oa[nt][0], oa[nt][1]);
                    *(unsigned*)(orow + 8 * nt) = *(unsigned*)&pk2;
                }
            }
        }
    }
}

// ---------------- launch ----------------
extern "C" void kernel_launch(void* const* d_in, const int* in_sizes, int n_in,
                              void* d_out, int out_size)
{
    const float* x          = (const float*)d_in[0];
    const float* pos        = (const float*)d_in[1];
    const float* in_proj_w  = (const float*)d_in[2];
    const float* in_proj_b  = (const float*)d_in[3];
    const float* out_proj_w = (const float*)d_in[4];
    const float* out_proj_b = (const float*)d_in[5];
    const float* ln1_w      = (const float*)d_in[6];
    const float* ln1_b      = (const float*)d_in[7];
    const float* ln2_w      = (const float*)d_in[8];
    const float* ln2_b      = (const float*)d_in[9];
    const float* ff1_w      = (const float*)d_in[10];
    const float* ff1_b      = (const float*)d_in[11];
    const float* ff2_w      = (const float*)d_in[12];
    const float* ff2_b      = (const float*)d_in[13];
    float* out = (float*)d_out;

    void *p_xpad, *p_z, *p_qkv, *p_o, *p_s2, *p_h, *p_g;
    void *p_wqkv, *p_wo, *p_w1, *p_w2;
    cudaGetSymbolAddress(&p_xpad, g_xpad);
    cudaGetSymbolAddress(&p_z,    g_z);
    cudaGetSymbolAddress(&p_qkv,  g_qkv);
    cudaGetSymbolAddress(&p_o,    g_o);
    cudaGetSymbolAddress(&p_s2,   g_s2);
    cudaGetSymbolAddress(&p_h,    g_h);
    cudaGetSymbolAddress(&p_g,    g_g);
    cudaGetSymbolAddress(&p_wqkv, g_wqkv);
    cudaGetSymbolAddress(&p_wo,   g_wo);
    cudaGetSymbolAddress(&p_w1,   g_w1);
    cudaGetSymbolAddress(&p_w2,   g_w2);

    float* xpad = (float*)p_xpad;
    __nv_bfloat16* z    = (__nv_bfloat16*)p_z;
    __nv_bfloat16* qkv  = (__nv_bfloat16*)p_qkv;
    __nv_bfloat16* o_   = (__nv_bfloat16*)p_o;
    float* s2 = (float*)p_s2;
    __nv_bfloat16* h_   = (__nv_bfloat16*)p_h;
    __nv_bfloat16* gbuf = (__nv_bfloat16*)p_g;
    __nv_bfloat16* wqkv = (__nv_bfloat16*)p_wqkv;
    __nv_bfloat16* wo   = (__nv_bfloat16*)p_wo;
    __nv_bfloat16* w1   = (__nv_bfloat16*)p_w1;
    __nv_bfloat16* w2   = (__nv_bfloat16*)p_w2;

    cudaFuncSetAttribute(gemm_mma<0>, cudaFuncAttributeMaxDynamicSharedMemorySize, GM_SMEM);
    cudaFuncSetAttribute(gemm_mma<1>, cudaFuncAttributeMaxDynamicSharedMemorySize, GM_SMEM);
    cudaFuncSetAttribute(gemm_mma<2>, cudaFuncAttributeMaxDynamicSharedMemorySize, GM_SMEM);
    cudaFuncSetAttribute(gemm_mma<3>, cudaFuncAttributeMaxDynamicSharedMemorySize, GM_SMEM);
    cudaFuncSetAttribute(attn_kernel, cudaFuncAttributeMaxDynamicSharedMemorySize, ATTN_SMEM);

    // weights -> bf16
    cvt_all_kernel<<<3072, 256>>>(in_proj_w, out_proj_w, ff1_w, ff2_w, wqkv, wo, w1, w2);

    // fused pad-transpose + LN1
    lnin_kernel<<<dim3(7, HP_, B_), dim3(32, 8)>>>(x, pos, ln1_w, ln1_b, xpad, z);

    // QKV GEMM
    gemm_mma<0><<<dim3(6, MT256), 256, GM_SMEM>>>(z, wqkv, in_proj_b, 256, 768,
                                                  qkv, nullptr, nullptr, nullptr);
    // attention
    attn_kernel<<<NWIN, 256, ATTN_SMEM>>>(qkv, o_);

    // out proj + residual(x+pos) -> s2
    gemm_mma<1><<<dim3(2, MT256), 256, GM_SMEM>>>(o_, wo, out_proj_b, 256, 256,
                                                  nullptr, s2, xpad, pos);
    // LN2
    ln_kernel<<<((int)M_TOT + 7) / 8, 256>>>(s2, ln2_w, ln2_b, h_, (int)M_TOT);

    // FF1 + gelu
    gemm_mma<2><<<dim3(8, MT256), 256, GM_SMEM>>>(h_, w1, ff1_b, 256, 1024,
                                                  gbuf, nullptr, nullptr, nullptr);
    // FF2 + residual -> direct NCHW cropped output
    gemm_mma<3><<<dim3(2, MT256), 256, GM_SMEM>>>(gbuf, w2, ff2_b, 1024, 256,
                                                  nullptr, out, s2, nullptr);
}